// round 2
// baseline (speedup 1.0000x reference)
#include <cuda_runtime.h>
#include <cuda_bf16.h>
#include <cstdint>

// Problem constants
#define BB 4
#define SS 2048
#define DD 1024
#define HH 16
#define DK 64
#define MM (BB * SS)   // 8192

// ---------------- scratch (device globals; no allocation) ----------------
__device__ float g_q[MM * DD];
__device__ float g_k[MM * DD];
__device__ float g_v[MM * DD];
__device__ float g_attn[MM * DD];

// ---------------- SGEMM: C = A[MxK] @ B[KxN] + bias[N] ----------------
#define BM 128
#define BN 128
#define BK 8
#define TM 8
#define TN 8

__global__ __launch_bounds__(256, 2)
void sgemm_bias(const float* __restrict__ A, const float* __restrict__ B,
                const float* __restrict__ bias, float* __restrict__ C,
                int M, int N, int K) {
    __shared__ float As[BK][BM + 4];
    __shared__ float Bs[BK][BN];

    const int tid = threadIdx.x;
    const int bx = blockIdx.x, by = blockIdx.y;
    const int row0 = by * BM, col0 = bx * BN;

    const int a_row = tid >> 1;          // 0..127
    const int a_col = (tid & 1) << 2;    // 0 or 4
    const int b_row = tid >> 5;          // 0..7
    const int b_col = (tid & 31) << 2;   // 0..124

    const int tx = tid & 15, ty = tid >> 4;

    float acc[TM][TN];
#pragma unroll
    for (int i = 0; i < TM; i++)
#pragma unroll
        for (int j = 0; j < TN; j++) acc[i][j] = 0.0f;

    for (int k0 = 0; k0 < K; k0 += BK) {
        float4 av = *(const float4*)&A[(size_t)(row0 + a_row) * K + k0 + a_col];
        As[a_col + 0][a_row] = av.x;
        As[a_col + 1][a_row] = av.y;
        As[a_col + 2][a_row] = av.z;
        As[a_col + 3][a_row] = av.w;
        float4 bv = *(const float4*)&B[(size_t)(k0 + b_row) * N + col0 + b_col];
        *(float4*)&Bs[b_row][b_col] = bv;
        __syncthreads();

#pragma unroll
        for (int k = 0; k < BK; k++) {
            float a[TM], b[TN];
            float4 a0 = *(const float4*)&As[k][ty * TM];
            float4 a1 = *(const float4*)&As[k][ty * TM + 4];
            a[0]=a0.x; a[1]=a0.y; a[2]=a0.z; a[3]=a0.w;
            a[4]=a1.x; a[5]=a1.y; a[6]=a1.z; a[7]=a1.w;
            float4 b0 = *(const float4*)&Bs[k][tx * TN];
            float4 b1 = *(const float4*)&Bs[k][tx * TN + 4];
            b[0]=b0.x; b[1]=b0.y; b[2]=b0.z; b[3]=b0.w;
            b[4]=b1.x; b[5]=b1.y; b[6]=b1.z; b[7]=b1.w;
#pragma unroll
            for (int i = 0; i < TM; i++)
#pragma unroll
                for (int j = 0; j < TN; j++)
                    acc[i][j] = fmaf(a[i], b[j], acc[i][j]);
        }
        __syncthreads();
    }

#pragma unroll
    for (int i = 0; i < TM; i++) {
        const int r = row0 + ty * TM + i;
#pragma unroll
        for (int j = 0; j < TN; j += 4) {
            const int c = col0 + tx * TN + j;
            float4 o;
            o.x = acc[i][j + 0] + bias[c + 0];
            o.y = acc[i][j + 1] + bias[c + 1];
            o.z = acc[i][j + 2] + bias[c + 2];
            o.w = acc[i][j + 3] + bias[c + 3];
            *(float4*)&C[(size_t)r * N + c] = o;
        }
    }
}

// ---------------- Flash attention (causal), fp32 ----------------
// Block: 256 threads (tx=tid%16 -> 4 cols, ty=tid/16 -> 4 rows).
// Q tile 64 rows; K tiles of 64; DK=64.
// Smem: QT[d][row] (64x68), KT/PT[*][*] (64x68, K transposed then reused for
// transposed P), V row-major (64x68), red[64][16].
#define FSTR 68

__global__ __launch_bounds__(256, 2)
void flash_causal(const float* __restrict__ Qg, const float* __restrict__ Kg,
                  const float* __restrict__ Vg, float* __restrict__ Og) {
    const int qt = blockIdx.x;        // 0..31
    const int bh = blockIdx.y;        // 0..63
    const int b  = bh >> 4;
    const int h  = bh & 15;
    const int tid = threadIdx.x;
    const int tx = tid & 15, ty = tid >> 4;
    const int q0 = qt * 64;

    extern __shared__ float sm[];
    float* QT = sm;                    // 64*68
    float* KT = QT + 64 * FSTR;        // 64*68 (reused as PT)
    float* Vs = KT + 64 * FSTR;        // 64*68
    float* red = Vs + 64 * FSTR;       // 64*16

    const float scale = 0.125f;        // 1/sqrt(64)
    const size_t base = ((size_t)b * SS) * DD + (size_t)h * DK;

    // Load Q tile transposed, pre-scaled.
    for (int i = tid; i < 64 * 16; i += 256) {
        const int r = i >> 4, c4 = (i & 15) << 2;
        float4 v4 = *(const float4*)&Qg[base + (size_t)(q0 + r) * DD + c4];
        QT[(c4 + 0) * FSTR + r] = v4.x * scale;
        QT[(c4 + 1) * FSTR + r] = v4.y * scale;
        QT[(c4 + 2) * FSTR + r] = v4.z * scale;
        QT[(c4 + 3) * FSTR + r] = v4.w * scale;
    }

    float m_i[4], l_i[4], Oa[4][4];
#pragma unroll
    for (int i = 0; i < 4; i++) {
        m_i[i] = -INFINITY; l_i[i] = 0.0f;
#pragma unroll
        for (int j = 0; j < 4; j++) Oa[i][j] = 0.0f;
    }

    for (int kt = 0; kt <= qt; kt++) {
        const int k0 = kt * 64;
        __syncthreads();  // previous PV done before overwriting KT/Vs

        // Load K tile transposed, V tile row-major.
        for (int i = tid; i < 64 * 16; i += 256) {
            const int r = i >> 4, c4 = (i & 15) << 2;
            float4 kv = *(const float4*)&Kg[base + (size_t)(k0 + r) * DD + c4];
            KT[(c4 + 0) * FSTR + r] = kv.x;
            KT[(c4 + 1) * FSTR + r] = kv.y;
            KT[(c4 + 2) * FSTR + r] = kv.z;
            KT[(c4 + 3) * FSTR + r] = kv.w;
            float4 vv = *(const float4*)&Vg[base + (size_t)(k0 + r) * DD + c4];
            *(float4*)&Vs[r * FSTR + c4] = vv;
        }
        __syncthreads();

        // S = (Q*scale) @ K^T : 4x4 per thread.
        float Sv[4][4];
#pragma unroll
        for (int i = 0; i < 4; i++)
#pragma unroll
            for (int j = 0; j < 4; j++) Sv[i][j] = 0.0f;

#pragma unroll 16
        for (int d = 0; d < 64; d++) {
            float4 aq = *(const float4*)&QT[d * FSTR + (ty << 2)];
            float4 bk = *(const float4*)&KT[d * FSTR + (tx << 2)];
            float a[4] = {aq.x, aq.y, aq.z, aq.w};
            float bvv[4] = {bk.x, bk.y, bk.z, bk.w};
#pragma unroll
            for (int i = 0; i < 4; i++)
#pragma unroll
                for (int j = 0; j < 4; j++)
                    Sv[i][j] = fmaf(a[i], bvv[j], Sv[i][j]);
        }

        // Causal mask (only diagonal tile needs it).
        if (kt == qt) {
#pragma unroll
            for (int i = 0; i < 4; i++)
#pragma unroll
                for (int j = 0; j < 4; j++)
                    if ((tx << 2) + j > (ty << 2) + i) Sv[i][j] = -INFINITY;
        }

        // Row max reduce across the 16 tx lanes.
        float rmax[4];
#pragma unroll
        for (int i = 0; i < 4; i++) {
            float m = fmaxf(fmaxf(Sv[i][0], Sv[i][1]), fmaxf(Sv[i][2], Sv[i][3]));
            red[((ty << 2) + i) * 16 + tx] = m;
        }
        __syncthreads();
#pragma unroll
        for (int i = 0; i < 4; i++) {
            float m = -INFINITY;
#pragma unroll
            for (int t = 0; t < 16; t++) m = fmaxf(m, red[((ty << 2) + i) * 16 + t]);
            rmax[i] = m;
        }
        __syncthreads();

        // Online softmax update.
        float m_new[4], alpha[4], rsum[4];
#pragma unroll
        for (int i = 0; i < 4; i++) {
            m_new[i] = fmaxf(m_i[i], rmax[i]);
            alpha[i] = __expf(m_i[i] - m_new[i]);
            float s = 0.0f;
#pragma unroll
            for (int j = 0; j < 4; j++) {
                Sv[i][j] = __expf(Sv[i][j] - m_new[i]);
                s += Sv[i][j];
            }
            rsum[i] = s;
            red[((ty << 2) + i) * 16 + tx] = s;
        }
        __syncthreads();
#pragma unroll
        for (int i = 0; i < 4; i++) {
            float s = 0.0f;
#pragma unroll
            for (int t = 0; t < 16; t++) s += red[((ty << 2) + i) * 16 + t];
            l_i[i] = l_i[i] * alpha[i] + s;
            m_i[i] = m_new[i];
#pragma unroll
            for (int j = 0; j < 4; j++) Oa[i][j] *= alpha[i];
        }

        // Write P transposed into KT's buffer (KT reads all done: 2 syncs above).
#pragma unroll
        for (int j = 0; j < 4; j++) {
            float4 p4;
            p4.x = Sv[0][j]; p4.y = Sv[1][j]; p4.z = Sv[2][j]; p4.w = Sv[3][j];
            *(float4*)&KT[((tx << 2) + j) * FSTR + (ty << 2)] = p4;
        }
        __syncthreads();

        // O += P @ V
#pragma unroll 16
        for (int j = 0; j < 64; j++) {
            float4 pv = *(const float4*)&KT[j * FSTR + (ty << 2)];
            float4 vv = *(const float4*)&Vs[j * FSTR + (tx << 2)];
            float p[4] = {pv.x, pv.y, pv.z, pv.w};
            float v[4] = {vv.x, vv.y, vv.z, vv.w};
#pragma unroll
            for (int i = 0; i < 4; i++)
#pragma unroll
                for (int jj = 0; jj < 4; jj++)
                    Oa[i][jj] = fmaf(p[i], v[jj], Oa[i][jj]);
        }
    }

    // Normalize + write out (layout [B,S,H,DK] == [B,S,D] with heads packed).
#pragma unroll
    for (int i = 0; i < 4; i++) {
        const float inv = 1.0f / l_i[i];
        float4 o;
        o.x = Oa[i][0] * inv; o.y = Oa[i][1] * inv;
        o.z = Oa[i][2] * inv; o.w = Oa[i][3] * inv;
        *(float4*)&Og[base + (size_t)(q0 + (ty << 2) + i) * DD + (tx << 2)] = o;
    }
}

// ---------------- launch ----------------
extern "C" void kernel_launch(void* const* d_in, const int* in_sizes, int n_in,
                              void* d_out, int out_size) {
    const float* Q   = (const float*)d_in[0];
    const float* K_V = (const float*)d_in[1];
    // d_in[2] = mask (structurally causal; applied analytically)
    const float* Wq = (const float*)d_in[3];
    const float* bq = (const float*)d_in[4];
    const float* Wk = (const float*)d_in[5];
    const float* bk = (const float*)d_in[6];
    const float* Wv = (const float*)d_in[7];
    const float* bv = (const float*)d_in[8];
    const float* Wo = (const float*)d_in[9];
    const float* bo = (const float*)d_in[10];
    float* out = (float*)d_out;

    float *q, *k, *v, *attn;
    cudaGetSymbolAddress((void**)&q, g_q);
    cudaGetSymbolAddress((void**)&k, g_k);
    cudaGetSymbolAddress((void**)&v, g_v);
    cudaGetSymbolAddress((void**)&attn, g_attn);

    dim3 gg(DD / BN, MM / BM);  // (8, 64)
    sgemm_bias<<<gg, 256>>>(Q,   Wq, bq, q, MM, DD, DD);
    sgemm_bias<<<gg, 256>>>(K_V, Wk, bk, k, MM, DD, DD);
    sgemm_bias<<<gg, 256>>>(K_V, Wv, bv, v, MM, DD, DD);

    size_t fsmem = (3 * 64 * FSTR + 64 * 16) * sizeof(float);
    cudaFuncSetAttribute(flash_causal, cudaFuncAttributeMaxDynamicSharedMemorySize, (int)fsmem);
    flash_causal<<<dim3(SS / 64, BB * HH), 256, fsmem>>>(q, k, v, attn);

    sgemm_bias<<<gg, 256>>>(attn, Wo, bo, out, MM, DD, DD);
}

// round 10
// speedup vs baseline: 2.5713x; 2.5713x over previous
#include <cuda_runtime.h>
#include <cuda_bf16.h>
#include <cstdint>

// Problem constants
#define BB 4
#define SS 2048
#define DD 1024
#define HH 16
#define DK 64
#define MM (BB * SS)   // 8192
#define K3 (3 * DD)    // 3072 expanded-K for hi/lo split GEMM

// ---------------- scratch (device globals; no allocation) ----------------
__device__ float g_q[MM * DD];
__device__ float g_k[MM * DD];
__device__ float g_v[MM * DD];
__device__ float g_attn[MM * DD];
__device__ __align__(16) __nv_bfloat16 g_aq[(size_t)MM * K3];   // Q expanded
__device__ __align__(16) __nv_bfloat16 g_akv[(size_t)MM * K3];  // K_V expanded
__device__ __align__(16) __nv_bfloat16 g_aat[(size_t)MM * K3];  // attn expanded
__device__ __align__(16) __nv_bfloat16 g_wq[DD * K3];
__device__ __align__(16) __nv_bfloat16 g_wk[DD * K3];
__device__ __align__(16) __nv_bfloat16 g_wv[DD * K3];
__device__ __align__(16) __nv_bfloat16 g_wo[DD * K3];

// ---------------- PTX helpers (sm_103 base target only; NO tcgen05) --------
__device__ __forceinline__ uint32_t smem_u32(const void* p) {
    uint32_t a;
    asm("{ .reg .u64 t; cvta.to.shared.u64 t, %1; cvt.u32.u64 %0, t; }" : "=r"(a) : "l"(p));
    return a;
}
__device__ __forceinline__ void cp_async16(uint32_t sm, const void* g) {
    asm volatile("cp.async.cg.shared.global [%0], [%1], 16;" :: "r"(sm), "l"(g));
}
#define CP_COMMIT() asm volatile("cp.async.commit_group;" ::: "memory")
#define CP_WAIT1()  asm volatile("cp.async.wait_group 1;" ::: "memory")

__device__ __forceinline__ void ldsm_x4(uint32_t& r0, uint32_t& r1, uint32_t& r2,
                                        uint32_t& r3, uint32_t addr) {
    asm volatile("ldmatrix.sync.aligned.m8n8.x4.shared.b16 {%0,%1,%2,%3}, [%4];"
                 : "=r"(r0), "=r"(r1), "=r"(r2), "=r"(r3) : "r"(addr));
}
__device__ __forceinline__ void mma16816(float* c, uint32_t a0, uint32_t a1,
                                         uint32_t a2, uint32_t a3,
                                         uint32_t b0, uint32_t b1) {
    asm volatile(
        "mma.sync.aligned.m16n8k16.row.col.f32.bf16.bf16.f32 "
        "{%0,%1,%2,%3}, {%4,%5,%6,%7}, {%8,%9}, {%0,%1,%2,%3};"
        : "+f"(c[0]), "+f"(c[1]), "+f"(c[2]), "+f"(c[3])
        : "r"(a0), "r"(a1), "r"(a2), "r"(a3), "r"(b0), "r"(b1));
}
__device__ __forceinline__ uint32_t sw128(uint32_t off) {
    return off ^ ((off >> 3) & 0x70);
}

// ---------------- conversion kernels ----------------
struct bf4 { __nv_bfloat16 v[4]; };  // 8 bytes

__global__ void conv_act(const float* __restrict__ src, __nv_bfloat16* __restrict__ dst) {
    size_t i = (size_t)blockIdx.x * 256 + threadIdx.x;      // group of 4 elements
    size_t row = i / (DD / 4);
    int c4 = (int)(i % (DD / 4)) * 4;
    float4 x = *(const float4*)(src + row * DD + c4);
    bf4 h, l;
    float xs[4] = {x.x, x.y, x.z, x.w};
#pragma unroll
    for (int j = 0; j < 4; j++) {
        __nv_bfloat16 hb = __float2bfloat16(xs[j]);
        h.v[j] = hb;
        l.v[j] = __float2bfloat16(xs[j] - __bfloat162float(hb));
    }
    size_t b = row * K3;
    *(bf4*)(dst + b + c4)          = h;
    *(bf4*)(dst + b + DD + c4)     = l;
    *(bf4*)(dst + b + 2 * DD + c4) = h;
}

// W [K=1024, N=1024] -> dst[n][k'] with k' blocks [hi | hi | lo]
__global__ void conv_w(const float* __restrict__ W, __nv_bfloat16* __restrict__ dst) {
    __shared__ float t[32][33];
    int k0 = blockIdx.x * 32, n0 = blockIdx.y * 32;
    int tx = threadIdx.x, ty = threadIdx.y;  // (32, 8)
#pragma unroll
    for (int r = 0; r < 4; r++)
        t[ty + 8 * r][tx] = W[(size_t)(k0 + ty + 8 * r) * DD + n0 + tx];
    __syncthreads();
#pragma unroll
    for (int r = 0; r < 4; r++) {
        int n = n0 + ty + 8 * r;
        float x = t[tx][ty + 8 * r];
        __nv_bfloat16 hb = __float2bfloat16(x);
        __nv_bfloat16 lb = __float2bfloat16(x - __bfloat162float(hb));
        size_t b = (size_t)n * K3 + k0 + tx;
        dst[b]          = hb;
        dst[b + DD]     = hb;
        dst[b + 2 * DD] = lb;
    }
}

// ---------------- HMMA GEMM: C[M,1024] = A'[M,3072] @ B'[1024,3072]^T + bias ----
// CTA 128x128, 8 warps (warp tile 64x32), K-chunk 64, 3-stage cp.async pipeline.
// A and B tiles stored [row][64 bf16] (128B rows) with SW128-style XOR swizzle.
#define GSTAGES 3
#define GCHUNKS (K3 / 64)        // 48
#define ATILE_BYTES (128 * 128)  // 128 rows x 128B = 16KB
#define STAGE_BYTES (2 * ATILE_BYTES)

__global__ __launch_bounds__(256, 2)
void gemm_mma(const __nv_bfloat16* __restrict__ A, const __nv_bfloat16* __restrict__ Bw,
              const float* __restrict__ bias, float* __restrict__ C) {
    extern __shared__ char dsm[];
    const int tid = threadIdx.x;
    const int wid = tid >> 5, lane = tid & 31;
    const int n0 = blockIdx.x * 128, m0 = blockIdx.y * 128;
    const int warp_m = (wid & 1) * 64;   // 0 or 64
    const int warp_n = (wid >> 1) * 32;  // 0..96

    uint32_t base = smem_u32(dsm);  // dynamic smem is 1024-aligned

    // cp.async mapping: thread u covers (row = u/8 + 32*pass, seg = u%8)
    const int ld_row = tid >> 3;        // 0..31
    const int ld_seg = tid & 7;         // 0..7

    auto load_chunk = [&](int c, int s) {
        uint32_t sA = base + s * STAGE_BYTES;
        uint32_t sB = sA + ATILE_BYTES;
        const __nv_bfloat16* Ab = A + (size_t)m0 * K3 + c * 64;
        const __nv_bfloat16* Bb = Bw + (size_t)n0 * K3 + c * 64;
#pragma unroll
        for (int p = 0; p < 4; p++) {
            int row = ld_row + 32 * p;
            uint32_t off = sw128((uint32_t)(row * 128 + ld_seg * 16));
            cp_async16(sA + off, Ab + (size_t)row * K3 + ld_seg * 8);
            cp_async16(sB + off, Bb + (size_t)row * K3 + ld_seg * 8);
        }
    };

    // ldmatrix lane-local offsets (tile-local bytes, pre-swizzle)
    const uint32_t a_lane = (uint32_t)((lane & 15) * 128 + (lane & 16));
    const uint32_t b_lane = (uint32_t)(((lane & 7) + ((lane & 16) >> 1)) * 128 + ((lane & 8) << 1));

    float acc[4][4][4];
#pragma unroll
    for (int i = 0; i < 4; i++)
#pragma unroll
        for (int j = 0; j < 4; j++)
#pragma unroll
            for (int e = 0; e < 4; e++) acc[i][j][e] = 0.0f;

    load_chunk(0, 0); CP_COMMIT();
    load_chunk(1, 1); CP_COMMIT();

    for (int c = 0; c < GCHUNKS; c++) {
        const int s = c % GSTAGES;
        CP_WAIT1();
        __syncthreads();

        uint32_t sA = base + s * STAGE_BYTES;
        uint32_t sB = sA + ATILE_BYTES;

#pragma unroll
        for (int step = 0; step < 4; step++) {
            const uint32_t kb = step * 32;
            // A fragments: 4 m-tiles of 16
            uint32_t af[4][4];
#pragma unroll
            for (int mt = 0; mt < 4; mt++) {
                uint32_t loc = (uint32_t)((warp_m + mt * 16) * 128) + a_lane + kb;
                ldsm_x4(af[mt][0], af[mt][1], af[mt][2], af[mt][3], sA + sw128(loc));
            }
            // B fragments: 4 n-tiles of 8, two ldmatrix.x4 (each covers 16 n rows)
            uint32_t bf[4][2];
#pragma unroll
            for (int bt = 0; bt < 2; bt++) {
                uint32_t loc = (uint32_t)((warp_n + bt * 16) * 128) + b_lane + kb;
                uint32_t r0, r1, r2, r3;
                ldsm_x4(r0, r1, r2, r3, sB + sw128(loc));
                bf[bt * 2 + 0][0] = r0; bf[bt * 2 + 0][1] = r1;
                bf[bt * 2 + 1][0] = r2; bf[bt * 2 + 1][1] = r3;
            }
#pragma unroll
            for (int mt = 0; mt < 4; mt++)
#pragma unroll
                for (int nt = 0; nt < 4; nt++)
                    mma16816(acc[mt][nt], af[mt][0], af[mt][1], af[mt][2], af[mt][3],
                             bf[nt][0], bf[nt][1]);
        }

        __syncthreads();
        const int cn = c + 2;
        if (cn < GCHUNKS) load_chunk(cn, cn % GSTAGES);
        CP_COMMIT();
    }

    // epilogue: thread holds C[m=mt*16 + lane/4 (+8)][n=nt*8 + 2*(lane%4) (+1)]
    const int mrow = lane >> 2, ncol = (lane & 3) * 2;
    float2 bv[4];
#pragma unroll
    for (int nt = 0; nt < 4; nt++) {
        int col = n0 + warp_n + nt * 8 + ncol;
        bv[nt].x = __ldg(&bias[col]);
        bv[nt].y = __ldg(&bias[col + 1]);
    }
#pragma unroll
    for (int mt = 0; mt < 4; mt++) {
        const int r0 = m0 + warp_m + mt * 16 + mrow;
#pragma unroll
        for (int nt = 0; nt < 4; nt++) {
            const int col = n0 + warp_n + nt * 8 + ncol;
            float2 o0, o1;
            o0.x = acc[mt][nt][0] + bv[nt].x;
            o0.y = acc[mt][nt][1] + bv[nt].y;
            o1.x = acc[mt][nt][2] + bv[nt].x;
            o1.y = acc[mt][nt][3] + bv[nt].y;
            *(float2*)&C[(size_t)r0 * DD + col] = o0;
            *(float2*)&C[(size_t)(r0 + 8) * DD + col] = o1;
        }
    }
}

// ---------------- Flash attention (causal), fp32 (unchanged) ----------------
#define FSTR 68

__global__ __launch_bounds__(256, 2)
void flash_causal(const float* __restrict__ Qg, const float* __restrict__ Kg,
                  const float* __restrict__ Vg, float* __restrict__ Og) {
    const int qt = blockIdx.x;
    const int bh = blockIdx.y;
    const int b  = bh >> 4;
    const int h  = bh & 15;
    const int tid = threadIdx.x;
    const int tx = tid & 15, ty = tid >> 4;
    const int q0 = qt * 64;

    extern __shared__ float sm[];
    float* QT = sm;
    float* KT = QT + 64 * FSTR;
    float* Vs = KT + 64 * FSTR;
    float* red = Vs + 64 * FSTR;

    const float scale = 0.125f;
    const size_t base = ((size_t)b * SS) * DD + (size_t)h * DK;

    for (int i = tid; i < 64 * 16; i += 256) {
        const int r = i >> 4, c4 = (i & 15) << 2;
        float4 v4 = *(const float4*)&Qg[base + (size_t)(q0 + r) * DD + c4];
        QT[(c4 + 0) * FSTR + r] = v4.x * scale;
        QT[(c4 + 1) * FSTR + r] = v4.y * scale;
        QT[(c4 + 2) * FSTR + r] = v4.z * scale;
        QT[(c4 + 3) * FSTR + r] = v4.w * scale;
    }

    float m_i[4], l_i[4], Oa[4][4];
#pragma unroll
    for (int i = 0; i < 4; i++) {
        m_i[i] = -INFINITY; l_i[i] = 0.0f;
#pragma unroll
        for (int j = 0; j < 4; j++) Oa[i][j] = 0.0f;
    }

    for (int kt = 0; kt <= qt; kt++) {
        const int k0 = kt * 64;
        __syncthreads();

        for (int i = tid; i < 64 * 16; i += 256) {
            const int r = i >> 4, c4 = (i & 15) << 2;
            float4 kv = *(const float4*)&Kg[base + (size_t)(k0 + r) * DD + c4];
            KT[(c4 + 0) * FSTR + r] = kv.x;
            KT[(c4 + 1) * FSTR + r] = kv.y;
            KT[(c4 + 2) * FSTR + r] = kv.z;
            KT[(c4 + 3) * FSTR + r] = kv.w;
            float4 vv = *(const float4*)&Vg[base + (size_t)(k0 + r) * DD + c4];
            *(float4*)&Vs[r * FSTR + c4] = vv;
        }
        __syncthreads();

        float Sv[4][4];
#pragma unroll
        for (int i = 0; i < 4; i++)
#pragma unroll
            for (int j = 0; j < 4; j++) Sv[i][j] = 0.0f;

#pragma unroll 16
        for (int d = 0; d < 64; d++) {
            float4 aq = *(const float4*)&QT[d * FSTR + (ty << 2)];
            float4 bk = *(const float4*)&KT[d * FSTR + (tx << 2)];
            float a[4] = {aq.x, aq.y, aq.z, aq.w};
            float bvv[4] = {bk.x, bk.y, bk.z, bk.w};
#pragma unroll
            for (int i = 0; i < 4; i++)
#pragma unroll
                for (int j = 0; j < 4; j++)
                    Sv[i][j] = fmaf(a[i], bvv[j], Sv[i][j]);
        }

        if (kt == qt) {
#pragma unroll
            for (int i = 0; i < 4; i++)
#pragma unroll
                for (int j = 0; j < 4; j++)
                    if ((tx << 2) + j > (ty << 2) + i) Sv[i][j] = -INFINITY;
        }

        float rmax[4];
#pragma unroll
        for (int i = 0; i < 4; i++) {
            float m = fmaxf(fmaxf(Sv[i][0], Sv[i][1]), fmaxf(Sv[i][2], Sv[i][3]));
            red[((ty << 2) + i) * 16 + tx] = m;
        }
        __syncthreads();
#pragma unroll
        for (int i = 0; i < 4; i++) {
            float m = -INFINITY;
#pragma unroll
            for (int t = 0; t < 16; t++) m = fmaxf(m, red[((ty << 2) + i) * 16 + t]);
            rmax[i] = m;
        }
        __syncthreads();

        float m_new[4], alpha[4];
#pragma unroll
        for (int i = 0; i < 4; i++) {
            m_new[i] = fmaxf(m_i[i], rmax[i]);
            alpha[i] = __expf(m_i[i] - m_new[i]);
            float s = 0.0f;
#pragma unroll
            for (int j = 0; j < 4; j++) {
                Sv[i][j] = __expf(Sv[i][j] - m_new[i]);
                s += Sv[i][j];
            }
            red[((ty << 2) + i) * 16 + tx] = s;
        }
        __syncthreads();
#pragma unroll
        for (int i = 0; i < 4; i++) {
            float s = 0.0f;
#pragma unroll
            for (int t = 0; t < 16; t++) s += red[((ty << 2) + i) * 16 + t];
            l_i[i] = l_i[i] * alpha[i] + s;
            m_i[i] = m_new[i];
#pragma unroll
            for (int j = 0; j < 4; j++) Oa[i][j] *= alpha[i];
        }

#pragma unroll
        for (int j = 0; j < 4; j++) {
            float4 p4;
            p4.x = Sv[0][j]; p4.y = Sv[1][j]; p4.z = Sv[2][j]; p4.w = Sv[3][j];
            *(float4*)&KT[((tx << 2) + j) * FSTR + (ty << 2)] = p4;
        }
        __syncthreads();

#pragma unroll 16
        for (int j = 0; j < 64; j++) {
            float4 pv = *(const float4*)&KT[j * FSTR + (ty << 2)];
            float4 vv = *(const float4*)&Vs[j * FSTR + (tx << 2)];
            float p[4] = {pv.x, pv.y, pv.z, pv.w};
            float v[4] = {vv.x, vv.y, vv.z, vv.w};
#pragma unroll
            for (int i = 0; i < 4; i++)
#pragma unroll
                for (int jj = 0; jj < 4; jj++)
                    Oa[i][jj] = fmaf(p[i], v[jj], Oa[i][jj]);
        }
    }

#pragma unroll
    for (int i = 0; i < 4; i++) {
        const float inv = 1.0f / l_i[i];
        float4 o;
        o.x = Oa[i][0] * inv; o.y = Oa[i][1] * inv;
        o.z = Oa[i][2] * inv; o.w = Oa[i][3] * inv;
        *(float4*)&Og[base + (size_t)(q0 + (ty << 2) + i) * DD + (tx << 2)] = o;
    }
}

// ---------------- launch ----------------
extern "C" void kernel_launch(void* const* d_in, const int* in_sizes, int n_in,
                              void* d_out, int out_size) {
    const float* Q   = (const float*)d_in[0];
    const float* K_V = (const float*)d_in[1];
    const float* Wq = (const float*)d_in[3];
    const float* bq = (const float*)d_in[4];
    const float* Wk = (const float*)d_in[5];
    const float* bk = (const float*)d_in[6];
    const float* Wv = (const float*)d_in[7];
    const float* bv = (const float*)d_in[8];
    const float* Wo = (const float*)d_in[9];
    const float* bo = (const float*)d_in[10];
    float* out = (float*)d_out;

    float *q, *k, *v, *attn;
    __nv_bfloat16 *aq, *akv, *aat, *wq, *wk, *wv, *wo;
    cudaGetSymbolAddress((void**)&q, g_q);
    cudaGetSymbolAddress((void**)&k, g_k);
    cudaGetSymbolAddress((void**)&v, g_v);
    cudaGetSymbolAddress((void**)&attn, g_attn);
    cudaGetSymbolAddress((void**)&aq, g_aq);
    cudaGetSymbolAddress((void**)&akv, g_akv);
    cudaGetSymbolAddress((void**)&aat, g_aat);
    cudaGetSymbolAddress((void**)&wq, g_wq);
    cudaGetSymbolAddress((void**)&wk, g_wk);
    cudaGetSymbolAddress((void**)&wv, g_wv);
    cudaGetSymbolAddress((void**)&wo, g_wo);

    const int gsmem = GSTAGES * STAGE_BYTES;  // 96KB
    cudaFuncSetAttribute(gemm_mma, cudaFuncAttributeMaxDynamicSharedMemorySize, gsmem);

    // weight conversion (transpose + hi/lo expand)
    dim3 wgrid(32, 32), wblk(32, 8);
    conv_w<<<wgrid, wblk>>>(Wq, wq);
    conv_w<<<wgrid, wblk>>>(Wk, wk);
    conv_w<<<wgrid, wblk>>>(Wv, wv);
    conv_w<<<wgrid, wblk>>>(Wo, wo);

    // activation conversion
    conv_act<<<MM * DD / 4 / 256, 256>>>(Q, aq);
    conv_act<<<MM * DD / 4 / 256, 256>>>(K_V, akv);

    // projections on tensor cores (HMMA)
    dim3 gg(DD / 128, MM / 128);  // (8, 64)
    gemm_mma<<<gg, 256, gsmem>>>(aq,  wq, bq, q);
    gemm_mma<<<gg, 256, gsmem>>>(akv, wk, bk, k);
    gemm_mma<<<gg, 256, gsmem>>>(akv, wv, bv, v);

    // attention
    size_t fsmem = (3 * 64 * FSTR + 64 * 16) * sizeof(float);
    cudaFuncSetAttribute(flash_causal, cudaFuncAttributeMaxDynamicSharedMemorySize, (int)fsmem);
    flash_causal<<<dim3(SS / 64, BB * HH), 256, fsmem>>>(q, k, v, attn);

    // output projection
    conv_act<<<MM * DD / 4 / 256, 256>>>(attn, aat);
    gemm_mma<<<gg, 256, gsmem>>>(aat, wo, bo, out);
}

// round 13
// speedup vs baseline: 4.8431x; 1.8835x over previous
#include <cuda_runtime.h>
#include <cuda_bf16.h>
#include <cstdint>

// Problem constants
#define BB 4
#define SS 2048
#define DD 1024
#define HH 16
#define DK 64
#define MM (BB * SS)   // 8192
#define K3 (3 * DD)    // 3072 expanded-K for hi/lo split GEMM

// ---------------- scratch (device globals; no allocation) ----------------
__device__ __align__(16) __nv_bfloat16 g_aq[(size_t)MM * K3];   // Q expanded
__device__ __align__(16) __nv_bfloat16 g_akv[(size_t)MM * K3];  // K_V expanded
__device__ __align__(16) __nv_bfloat16 g_aat[(size_t)MM * K3];  // attn out expanded
__device__ __align__(16) __nv_bfloat16 g_wq[DD * K3];
__device__ __align__(16) __nv_bfloat16 g_wk[DD * K3];
__device__ __align__(16) __nv_bfloat16 g_wv[DD * K3];
__device__ __align__(16) __nv_bfloat16 g_wo[DD * K3];
// hi/lo bf16 projections (q pre-scaled by 0.125)
__device__ __align__(16) __nv_bfloat16 g_qh[(size_t)MM * DD];
__device__ __align__(16) __nv_bfloat16 g_ql[(size_t)MM * DD];
__device__ __align__(16) __nv_bfloat16 g_kh[(size_t)MM * DD];
__device__ __align__(16) __nv_bfloat16 g_kl[(size_t)MM * DD];
__device__ __align__(16) __nv_bfloat16 g_vh[(size_t)MM * DD];
__device__ __align__(16) __nv_bfloat16 g_vl[(size_t)MM * DD];

// ---------------- PTX helpers (sm_103 base target; NO tcgen05) --------
__device__ __forceinline__ uint32_t smem_u32(const void* p) {
    uint32_t a;
    asm("{ .reg .u64 t; cvta.to.shared.u64 t, %1; cvt.u32.u64 %0, t; }" : "=r"(a) : "l"(p));
    return a;
}
__device__ __forceinline__ void cp_async16(uint32_t sm, const void* g) {
    asm volatile("cp.async.cg.shared.global [%0], [%1], 16;" :: "r"(sm), "l"(g));
}
#define CP_COMMIT() asm volatile("cp.async.commit_group;" ::: "memory")
#define CP_WAIT1()  asm volatile("cp.async.wait_group 1;" ::: "memory")
#define CP_WAIT0()  asm volatile("cp.async.wait_group 0;" ::: "memory")

__device__ __forceinline__ void ldsm_x4(uint32_t& r0, uint32_t& r1, uint32_t& r2,
                                        uint32_t& r3, uint32_t addr) {
    asm volatile("ldmatrix.sync.aligned.m8n8.x4.shared.b16 {%0,%1,%2,%3}, [%4];"
                 : "=r"(r0), "=r"(r1), "=r"(r2), "=r"(r3) : "r"(addr));
}
__device__ __forceinline__ void ldsm_x4_t(uint32_t& r0, uint32_t& r1, uint32_t& r2,
                                          uint32_t& r3, uint32_t addr) {
    asm volatile("ldmatrix.sync.aligned.m8n8.x4.trans.shared.b16 {%0,%1,%2,%3}, [%4];"
                 : "=r"(r0), "=r"(r1), "=r"(r2), "=r"(r3) : "r"(addr));
}
__device__ __forceinline__ void mma16816(float* c, uint32_t a0, uint32_t a1,
                                         uint32_t a2, uint32_t a3,
                                         uint32_t b0, uint32_t b1) {
    asm volatile(
        "mma.sync.aligned.m16n8k16.row.col.f32.bf16.bf16.f32 "
        "{%0,%1,%2,%3}, {%4,%5,%6,%7}, {%8,%9}, {%0,%1,%2,%3};"
        : "+f"(c[0]), "+f"(c[1]), "+f"(c[2]), "+f"(c[3])
        : "r"(a0), "r"(a1), "r"(a2), "r"(a3), "r"(b0), "r"(b1));
}
__device__ __forceinline__ uint32_t sw128(uint32_t off) {
    return off ^ ((off >> 3) & 0x70);
}
__device__ __forceinline__ uint32_t pack_bf2(float x, float y) {
    __nv_bfloat162 t = __float22bfloat162_rn(make_float2(x, y));
    return *(uint32_t*)&t;
}

// ---------------- conversion kernels ----------------
struct bf4 { __nv_bfloat16 v[4]; };  // 8 bytes

__global__ void conv_act(const float* __restrict__ src, __nv_bfloat16* __restrict__ dst) {
    size_t i = (size_t)blockIdx.x * 256 + threadIdx.x;
    size_t row = i / (DD / 4);
    int c4 = (int)(i % (DD / 4)) * 4;
    float4 x = *(const float4*)(src + row * DD + c4);
    bf4 h, l;
    float xs[4] = {x.x, x.y, x.z, x.w};
#pragma unroll
    for (int j = 0; j < 4; j++) {
        __nv_bfloat16 hb = __float2bfloat16(xs[j]);
        h.v[j] = hb;
        l.v[j] = __float2bfloat16(xs[j] - __bfloat162float(hb));
    }
    size_t b = row * K3;
    *(bf4*)(dst + b + c4)          = h;
    *(bf4*)(dst + b + DD + c4)     = l;
    *(bf4*)(dst + b + 2 * DD + c4) = h;
}

// W [K=1024, N=1024] -> dst[n][k'] with k' blocks [hi | hi | lo]
__global__ void conv_w(const float* __restrict__ W, __nv_bfloat16* __restrict__ dst) {
    __shared__ float t[32][33];
    int k0 = blockIdx.x * 32, n0 = blockIdx.y * 32;
    int tx = threadIdx.x, ty = threadIdx.y;  // (32, 8)
#pragma unroll
    for (int r = 0; r < 4; r++)
        t[ty + 8 * r][tx] = W[(size_t)(k0 + ty + 8 * r) * DD + n0 + tx];
    __syncthreads();
#pragma unroll
    for (int r = 0; r < 4; r++) {
        int n = n0 + ty + 8 * r;
        float x = t[tx][ty + 8 * r];
        __nv_bfloat16 hb = __float2bfloat16(x);
        __nv_bfloat16 lb = __float2bfloat16(x - __bfloat162float(hb));
        size_t b = (size_t)n * K3 + k0 + tx;
        dst[b]          = hb;
        dst[b + DD]     = hb;
        dst[b + 2 * DD] = lb;
    }
}

// ---------------- HMMA GEMM core (shared mainloop) ----------------
#define GSTAGES 3
#define GCHUNKS (K3 / 64)        // 48
#define ATILE_BYTES (128 * 128)  // 16KB
#define STAGE_BYTES (2 * ATILE_BYTES)

struct GemmCore {
    float acc[4][4][4];
    int n0, m0, warp_m, warp_n, lane;
};

__device__ __forceinline__ void gemm_mainloop(
    GemmCore& gc, const __nv_bfloat16* __restrict__ A,
    const __nv_bfloat16* __restrict__ Bw, char* dsm) {
    const int tid = threadIdx.x;
    const int wid = tid >> 5;
    gc.lane = tid & 31;
    gc.n0 = blockIdx.x * 128; gc.m0 = blockIdx.y * 128;
    gc.warp_m = (wid & 1) * 64;
    gc.warp_n = (wid >> 1) * 32;
    uint32_t base = smem_u32(dsm);
    const int ld_row = tid >> 3, ld_seg = tid & 7;

    auto load_chunk = [&](int c, int s) {
        uint32_t sA = base + s * STAGE_BYTES;
        uint32_t sB = sA + ATILE_BYTES;
        const __nv_bfloat16* Ab = A + (size_t)gc.m0 * K3 + c * 64;
        const __nv_bfloat16* Bb = Bw + (size_t)gc.n0 * K3 + c * 64;
#pragma unroll
        for (int p = 0; p < 4; p++) {
            int row = ld_row + 32 * p;
            uint32_t off = sw128((uint32_t)(row * 128 + ld_seg * 16));
            cp_async16(sA + off, Ab + (size_t)row * K3 + ld_seg * 8);
            cp_async16(sB + off, Bb + (size_t)row * K3 + ld_seg * 8);
        }
    };

    const uint32_t a_lane = (uint32_t)((gc.lane & 15) * 128 + (gc.lane & 16));
    const uint32_t b_lane = (uint32_t)(((gc.lane & 7) + ((gc.lane & 16) >> 1)) * 128 +
                                       ((gc.lane & 8) << 1));
#pragma unroll
    for (int i = 0; i < 4; i++)
#pragma unroll
        for (int j = 0; j < 4; j++)
#pragma unroll
            for (int e = 0; e < 4; e++) gc.acc[i][j][e] = 0.0f;

    load_chunk(0, 0); CP_COMMIT();
    load_chunk(1, 1); CP_COMMIT();

    for (int c = 0; c < GCHUNKS; c++) {
        const int s = c % GSTAGES;
        CP_WAIT1();
        __syncthreads();
        uint32_t sA = base + s * STAGE_BYTES;
        uint32_t sB = sA + ATILE_BYTES;
#pragma unroll
        for (int step = 0; step < 4; step++) {
            const uint32_t kb = step * 32;
            uint32_t af[4][4];
#pragma unroll
            for (int mt = 0; mt < 4; mt++) {
                uint32_t loc = (uint32_t)((gc.warp_m + mt * 16) * 128) + a_lane + kb;
                ldsm_x4(af[mt][0], af[mt][1], af[mt][2], af[mt][3], sA + sw128(loc));
            }
            uint32_t bf[4][2];
#pragma unroll
            for (int bt = 0; bt < 2; bt++) {
                uint32_t loc = (uint32_t)((gc.warp_n + bt * 16) * 128) + b_lane + kb;
                uint32_t r0, r1, r2, r3;
                ldsm_x4(r0, r1, r2, r3, sB + sw128(loc));
                bf[bt * 2 + 0][0] = r0; bf[bt * 2 + 0][1] = r1;
                bf[bt * 2 + 1][0] = r2; bf[bt * 2 + 1][1] = r3;
            }
#pragma unroll
            for (int mt = 0; mt < 4; mt++)
#pragma unroll
                for (int nt = 0; nt < 4; nt++)
                    mma16816(gc.acc[mt][nt], af[mt][0], af[mt][1], af[mt][2], af[mt][3],
                             bf[nt][0], bf[nt][1]);
        }
        __syncthreads();
        const int cn = c + 2;
        if (cn < GCHUNKS) load_chunk(cn, cn % GSTAGES);
        CP_COMMIT();
    }
}

// fp32-output GEMM (final Wo projection)
__global__ __launch_bounds__(256, 2)
void gemm_mma(const __nv_bfloat16* __restrict__ A, const __nv_bfloat16* __restrict__ Bw,
              const float* __restrict__ bias, float* __restrict__ C) {
    extern __shared__ char dsm[];
    GemmCore gc;
    gemm_mainloop(gc, A, Bw, dsm);
    const int mrow = gc.lane >> 2, ncol = (gc.lane & 3) * 2;
    float2 bv[4];
#pragma unroll
    for (int nt = 0; nt < 4; nt++) {
        int col = gc.n0 + gc.warp_n + nt * 8 + ncol;
        bv[nt].x = __ldg(&bias[col]);
        bv[nt].y = __ldg(&bias[col + 1]);
    }
#pragma unroll
    for (int mt = 0; mt < 4; mt++) {
        const int r0 = gc.m0 + gc.warp_m + mt * 16 + mrow;
#pragma unroll
        for (int nt = 0; nt < 4; nt++) {
            const int col = gc.n0 + gc.warp_n + nt * 8 + ncol;
            float2 o0, o1;
            o0.x = gc.acc[mt][nt][0] + bv[nt].x;
            o0.y = gc.acc[mt][nt][1] + bv[nt].y;
            o1.x = gc.acc[mt][nt][2] + bv[nt].x;
            o1.y = gc.acc[mt][nt][3] + bv[nt].y;
            *(float2*)&C[(size_t)r0 * DD + col] = o0;
            *(float2*)&C[(size_t)(r0 + 8) * DD + col] = o1;
        }
    }
}

// bf16 hi/lo output GEMM (q/k/v projections); scale folded (0.125 for q)
__global__ __launch_bounds__(256, 2)
void gemm_mma_hl(const __nv_bfloat16* __restrict__ A, const __nv_bfloat16* __restrict__ Bw,
                 const float* __restrict__ bias, __nv_bfloat16* __restrict__ Ch,
                 __nv_bfloat16* __restrict__ Cl, float scale) {
    extern __shared__ char dsm[];
    GemmCore gc;
    gemm_mainloop(gc, A, Bw, dsm);
    const int mrow = gc.lane >> 2, ncol = (gc.lane & 3) * 2;
    float2 bv[4];
#pragma unroll
    for (int nt = 0; nt < 4; nt++) {
        int col = gc.n0 + gc.warp_n + nt * 8 + ncol;
        bv[nt].x = __ldg(&bias[col]);
        bv[nt].y = __ldg(&bias[col + 1]);
    }
#pragma unroll
    for (int mt = 0; mt < 4; mt++) {
        const int r0 = gc.m0 + gc.warp_m + mt * 16 + mrow;
#pragma unroll
        for (int nt = 0; nt < 4; nt++) {
            const int col = gc.n0 + gc.warp_n + nt * 8 + ncol;
#pragma unroll
            for (int half = 0; half < 2; half++) {
                const int r = r0 + half * 8;
                float vx = (gc.acc[mt][nt][2 * half + 0] + bv[nt].x) * scale;
                float vy = (gc.acc[mt][nt][2 * half + 1] + bv[nt].y) * scale;
                __nv_bfloat162 h2 = __float22bfloat162_rn(make_float2(vx, vy));
                float lx = vx - __bfloat162float(h2.x);
                float ly = vy - __bfloat162float(h2.y);
                __nv_bfloat162 l2 = __float22bfloat162_rn(make_float2(lx, ly));
                *(__nv_bfloat162*)&Ch[(size_t)r * DD + col] = h2;
                *(__nv_bfloat162*)&Cl[(size_t)r * DD + col] = l2;
            }
        }
    }
}

// ---------------- HMMA flash attention (causal) ----------------
// CTA: 128 q rows, 8 warps (m16 each), kv tiles of 64, double-buffered.
// Smem: qh/ql 32KB + 2 stages x (kh,kl,vh,vl = 32KB) = 96KB (+align pad).
#define FSM_Q 32768
#define FSM_STAGE 32768

__global__ __launch_bounds__(256, 2)
void flash_hmma(const __nv_bfloat16* __restrict__ Qh, const __nv_bfloat16* __restrict__ Ql,
                const __nv_bfloat16* __restrict__ Kh, const __nv_bfloat16* __restrict__ Kl,
                const __nv_bfloat16* __restrict__ Vh, const __nv_bfloat16* __restrict__ Vl,
                __nv_bfloat16* __restrict__ aat) {
    const int qi = (int)(gridDim.x - 1) - (int)blockIdx.x;  // heavy CTAs first
    const int bh = blockIdx.y;
    const int b = bh >> 4, h = bh & 15;
    const int tid = threadIdx.x;
    const int w = tid >> 5, lane = tid & 31;

    extern __shared__ char dsm[];
    uint32_t sq = (smem_u32(dsm) + 1023) & ~1023u;
    uint32_t skv = sq + FSM_Q;

    const size_t rowbase = (size_t)b * SS;
    const int colh = h * 64;

    // load q hi/lo tiles (128 rows x 64 bf16 each)
    {
        int row = tid >> 1;
        int s0 = (tid & 1) * 4;
        const __nv_bfloat16* srcH = Qh + (rowbase + (size_t)qi * 128 + row) * DD + colh;
        const __nv_bfloat16* srcL = Ql + (rowbase + (size_t)qi * 128 + row) * DD + colh;
#pragma unroll
        for (int s = 0; s < 4; s++) {
            uint32_t off = sw128((uint32_t)(row * 128 + (s0 + s) * 16));
            cp_async16(sq + off, srcH + (s0 + s) * 8);
            cp_async16(sq + 16384 + off, srcL + (s0 + s) * 8);
        }
    }

    const int nt_kv = 2 * qi + 2;
    auto load_kv = [&](int kt, int st) {
        uint32_t sb = skv + st * FSM_STAGE;
        int row = tid >> 2, sg = tid & 3;
        size_t grow = (rowbase + (size_t)kt * 64 + row) * DD + colh;
        const __nv_bfloat16* arrs[4] = {Kh + grow, Kl + grow, Vh + grow, Vl + grow};
#pragma unroll
        for (int a = 0; a < 4; a++)
#pragma unroll
            for (int j = 0; j < 2; j++) {
                int seg = sg + j * 4;
                cp_async16(sb + a * 8192 + sw128((uint32_t)(row * 128 + seg * 16)),
                           arrs[a] + seg * 8);
            }
    };
    load_kv(0, 0);
    CP_COMMIT();

    const uint32_t a_lane = (uint32_t)((lane & 15) * 128 + (lane & 16));
    const uint32_t b_lane = (uint32_t)(((lane & 7) + ((lane & 16) >> 1)) * 128 +
                                       ((lane & 8) << 1));
    const uint32_t v_lane = (uint32_t)((lane & 15) * 128 + (lane & 16));

    float O[8][4];
#pragma unroll
    for (int nt = 0; nt < 8; nt++)
#pragma unroll
        for (int e = 0; e < 4; e++) O[nt][e] = 0.0f;
    float mA = -INFINITY, mB = -INFINITY, lA = 0.0f, lB = 0.0f;

    for (int kt = 0; kt < nt_kv; kt++) {
        if (kt + 1 < nt_kv) {
            load_kv(kt + 1, (kt + 1) & 1);
            CP_COMMIT();
            CP_WAIT1();
        } else {
            CP_WAIT0();
        }
        __syncthreads();

        uint32_t sKH = skv + (kt & 1) * FSM_STAGE;
        uint32_t sKL = sKH + 8192;
        uint32_t sVH = sKH + 16384;
        uint32_t sVL = sKH + 24576;

        // ---- S = q·kᵀ (3-term hi/lo) ----
        float S[8][4];
#pragma unroll
        for (int nt = 0; nt < 8; nt++)
#pragma unroll
            for (int e = 0; e < 4; e++) S[nt][e] = 0.0f;

#pragma unroll
        for (int c = 0; c < 4; c++) {
            uint32_t aloc = (uint32_t)(w * 16 * 128) + a_lane + c * 32;
            uint32_t qhf[4], qlf[4];
            ldsm_x4(qhf[0], qhf[1], qhf[2], qhf[3], sq + sw128(aloc));
            ldsm_x4(qlf[0], qlf[1], qlf[2], qlf[3], sq + 16384 + sw128(aloc));
#pragma unroll
            for (int nt2 = 0; nt2 < 4; nt2++) {
                uint32_t loc = (uint32_t)(nt2 * 16 * 128) + b_lane + c * 32;
                uint32_t h0, h1, h2, h3, l0, l1, l2, l3;
                ldsm_x4(h0, h1, h2, h3, sKH + sw128(loc));
                ldsm_x4(l0, l1, l2, l3, sKL + sw128(loc));
                mma16816(S[2 * nt2 + 0], qhf[0], qhf[1], qhf[2], qhf[3], h0, h1);
                mma16816(S[2 * nt2 + 1], qhf[0], qhf[1], qhf[2], qhf[3], h2, h3);
                mma16816(S[2 * nt2 + 0], qlf[0], qlf[1], qlf[2], qlf[3], h0, h1);
                mma16816(S[2 * nt2 + 1], qlf[0], qlf[1], qlf[2], qlf[3], h2, h3);
                mma16816(S[2 * nt2 + 0], qhf[0], qhf[1], qhf[2], qhf[3], l0, l1);
                mma16816(S[2 * nt2 + 1], qhf[0], qhf[1], qhf[2], qhf[3], l2, l3);
            }
        }

        // ---- causal mask (partial tiles only) ----
        if (kt >= 2 * qi) {
            const int row0 = qi * 128 + w * 16 + (lane >> 2);
            const int col0 = kt * 64 + 2 * (lane & 3);
#pragma unroll
            for (int nt = 0; nt < 8; nt++)
#pragma unroll
                for (int e = 0; e < 2; e++) {
                    int col = col0 + nt * 8 + e;
                    if (col > row0) S[nt][e] = -1e30f;
                    if (col > row0 + 8) S[nt][2 + e] = -1e30f;
                }
        }

        // ---- online softmax (rows rA=lane/4, rB=rA+8 per warp) ----
        float tmA = -INFINITY, tmB = -INFINITY;
#pragma unroll
        for (int nt = 0; nt < 8; nt++) {
            tmA = fmaxf(tmA, fmaxf(S[nt][0], S[nt][1]));
            tmB = fmaxf(tmB, fmaxf(S[nt][2], S[nt][3]));
        }
        tmA = fmaxf(tmA, __shfl_xor_sync(0xffffffffu, tmA, 1));
        tmA = fmaxf(tmA, __shfl_xor_sync(0xffffffffu, tmA, 2));
        tmB = fmaxf(tmB, __shfl_xor_sync(0xffffffffu, tmB, 1));
        tmB = fmaxf(tmB, __shfl_xor_sync(0xffffffffu, tmB, 2));

        float mnA = fmaxf(mA, tmA), mnB = fmaxf(mB, tmB);
        float alA = __expf(mA - mnA), alB = __expf(mB - mnB);
        mA = mnA; mB = mnB;

        float rsA = 0.0f, rsB = 0.0f;
#pragma unroll
        for (int nt = 0; nt < 8; nt++) {
            S[nt][0] = __expf(S[nt][0] - mnA); rsA += S[nt][0];
            S[nt][1] = __expf(S[nt][1] - mnA); rsA += S[nt][1];
            S[nt][2] = __expf(S[nt][2] - mnB); rsB += S[nt][2];
            S[nt][3] = __expf(S[nt][3] - mnB); rsB += S[nt][3];
        }
        rsA += __shfl_xor_sync(0xffffffffu, rsA, 1);
        rsA += __shfl_xor_sync(0xffffffffu, rsA, 2);
        rsB += __shfl_xor_sync(0xffffffffu, rsB, 1);
        rsB += __shfl_xor_sync(0xffffffffu, rsB, 2);
        lA = lA * alA + rsA;
        lB = lB * alB + rsB;
#pragma unroll
        for (int nt = 0; nt < 8; nt++) {
            O[nt][0] *= alA; O[nt][1] *= alA;
            O[nt][2] *= alB; O[nt][3] *= alB;
        }

        // ---- O += P·V (3-term hi/lo; P from registers) ----
#pragma unroll
        for (int c = 0; c < 4; c++) {
            // A frags for k16 chunk c (S n-tiles 2c, 2c+1)
            uint32_t ph[4], pl[4];
#pragma unroll
            for (int half = 0; half < 2; half++) {
                const float s0 = S[2 * c + half][0], s1 = S[2 * c + half][1];
                const float s2 = S[2 * c + half][2], s3 = S[2 * c + half][3];
                uint32_t h01 = pack_bf2(s0, s1);
                uint32_t h23 = pack_bf2(s2, s3);
                __nv_bfloat162 hb01 = *(__nv_bfloat162*)&h01;
                __nv_bfloat162 hb23 = *(__nv_bfloat162*)&h23;
                uint32_t l01 = pack_bf2(s0 - __bfloat162float(hb01.x),
                                        s1 - __bfloat162float(hb01.y));
                uint32_t l23 = pack_bf2(s2 - __bfloat162float(hb23.x),
                                        s3 - __bfloat162float(hb23.y));
                ph[2 * half + 0] = h01; ph[2 * half + 1] = h23;
                pl[2 * half + 0] = l01; pl[2 * half + 1] = l23;
            }
            // wait: A frag order is a0(row,k0-7) a1(row+8,k0-7) a2(row,k8-15) a3(row+8,k8-15)
            // our mapping: a0=ntile2c(c0,c1) a1=ntile2c(c2,c3) a2=ntile2c+1(c0,c1) a3=...
            // That matches {h01(2c), h23(2c), h01(2c+1), h23(2c+1)} as built above. ✓
#pragma unroll
            for (int nt2 = 0; nt2 < 4; nt2++) {
                uint32_t loc = (uint32_t)(c * 16 * 128 + nt2 * 32) + v_lane;
                uint32_t he0, he1, ho0, ho1, le0, le1, lo0, lo1;
                ldsm_x4_t(he0, he1, ho0, ho1, sVH + sw128(loc));
                ldsm_x4_t(le0, le1, lo0, lo1, sVL + sw128(loc));
                mma16816(O[2 * nt2 + 0], ph[0], ph[1], ph[2], ph[3], he0, he1);
                mma16816(O[2 * nt2 + 1], ph[0], ph[1], ph[2], ph[3], ho0, ho1);
                mma16816(O[2 * nt2 + 0], pl[0], pl[1], pl[2], pl[3], he0, he1);
                mma16816(O[2 * nt2 + 1], pl[0], pl[1], pl[2], pl[3], ho0, ho1);
                mma16816(O[2 * nt2 + 0], ph[0], ph[1], ph[2], ph[3], le0, le1);
                mma16816(O[2 * nt2 + 1], ph[0], ph[1], ph[2], ph[3], lo0, lo1);
            }
        }
        __syncthreads();
    }

    // ---- epilogue: normalize, write expanded [hi | lo | hi] into aat ----
    const float invA = 1.0f / lA, invB = 1.0f / lB;
    const int rA = b * SS + qi * 128 + w * 16 + (lane >> 2);
    const int rB = rA + 8;
    const int cb = colh + 2 * (lane & 3);
#pragma unroll
    for (int nt = 0; nt < 8; nt++) {
        const int col = cb + nt * 8;
        // row A
        {
            float vx = O[nt][0] * invA, vy = O[nt][1] * invA;
            __nv_bfloat162 h2 = __float22bfloat162_rn(make_float2(vx, vy));
            __nv_bfloat162 l2 = __float22bfloat162_rn(
                make_float2(vx - __bfloat162float(h2.x), vy - __bfloat162float(h2.y)));
            __nv_bfloat16* base = aat + (size_t)rA * K3;
            *(__nv_bfloat162*)(base + col) = h2;
            *(__nv_bfloat162*)(base + DD + col) = l2;
            *(__nv_bfloat162*)(base + 2 * DD + col) = h2;
        }
        // row B
        {
            float vx = O[nt][2] * invB, vy = O[nt][3] * invB;
            __nv_bfloat162 h2 = __float22bfloat162_rn(make_float2(vx, vy));
            __nv_bfloat162 l2 = __float22bfloat162_rn(
                make_float2(vx - __bfloat162float(h2.x), vy - __bfloat162float(h2.y)));
            __nv_bfloat16* base = aat + (size_t)rB * K3;
            *(__nv_bfloat162*)(base + col) = h2;
            *(__nv_bfloat162*)(base + DD + col) = l2;
            *(__nv_bfloat162*)(base + 2 * DD + col) = h2;
        }
    }
}

// ---------------- launch ----------------
extern "C" void kernel_launch(void* const* d_in, const int* in_sizes, int n_in,
                              void* d_out, int out_size) {
    const float* Q   = (const float*)d_in[0];
    const float* K_V = (const float*)d_in[1];
    const float* Wq = (const float*)d_in[3];
    const float* bq = (const float*)d_in[4];
    const float* Wk = (const float*)d_in[5];
    const float* bk = (const float*)d_in[6];
    const float* Wv = (const float*)d_in[7];
    const float* bv = (const float*)d_in[8];
    const float* Wo = (const float*)d_in[9];
    const float* bo = (const float*)d_in[10];
    float* out = (float*)d_out;

    __nv_bfloat16 *aq, *akv, *aat, *wq, *wk, *wv, *wo;
    __nv_bfloat16 *qh, *ql, *kh, *kl, *vh, *vl;
    cudaGetSymbolAddress((void**)&aq, g_aq);
    cudaGetSymbolAddress((void**)&akv, g_akv);
    cudaGetSymbolAddress((void**)&aat, g_aat);
    cudaGetSymbolAddress((void**)&wq, g_wq);
    cudaGetSymbolAddress((void**)&wk, g_wk);
    cudaGetSymbolAddress((void**)&wv, g_wv);
    cudaGetSymbolAddress((void**)&wo, g_wo);
    cudaGetSymbolAddress((void**)&qh, g_qh);
    cudaGetSymbolAddress((void**)&ql, g_ql);
    cudaGetSymbolAddress((void**)&kh, g_kh);
    cudaGetSymbolAddress((void**)&kl, g_kl);
    cudaGetSymbolAddress((void**)&vh, g_vh);
    cudaGetSymbolAddress((void**)&vl, g_vl);

    const int gsmem = GSTAGES * STAGE_BYTES;  // 96KB
    cudaFuncSetAttribute(gemm_mma, cudaFuncAttributeMaxDynamicSharedMemorySize, gsmem);
    cudaFuncSetAttribute(gemm_mma_hl, cudaFuncAttributeMaxDynamicSharedMemorySize, gsmem);
    const int fsmem = FSM_Q + 2 * FSM_STAGE + 1024;  // 97KB
    cudaFuncSetAttribute(flash_hmma, cudaFuncAttributeMaxDynamicSharedMemorySize, fsmem);

    // conversions
    dim3 wgrid(32, 32), wblk(32, 8);
    conv_w<<<wgrid, wblk>>>(Wq, wq);
    conv_w<<<wgrid, wblk>>>(Wk, wk);
    conv_w<<<wgrid, wblk>>>(Wv, wv);
    conv_w<<<wgrid, wblk>>>(Wo, wo);
    conv_act<<<MM * DD / 4 / 256, 256>>>(Q, aq);
    conv_act<<<MM * DD / 4 / 256, 256>>>(K_V, akv);

    // projections -> bf16 hi/lo (q pre-scaled by 1/sqrt(dk)=0.125)
    dim3 gg(DD / 128, MM / 128);
    gemm_mma_hl<<<gg, 256, gsmem>>>(aq,  wq, bq, qh, ql, 0.125f);
    gemm_mma_hl<<<gg, 256, gsmem>>>(akv, wk, bk, kh, kl, 1.0f);
    gemm_mma_hl<<<gg, 256, gsmem>>>(akv, wv, bv, vh, vl, 1.0f);

    // flash attention -> expanded aat
    flash_hmma<<<dim3(SS / 128, BB * HH), 256, fsmem>>>(qh, ql, kh, kl, vh, vl, aat);

    // output projection (fp32 out)
    gemm_mma<<<gg, 256, gsmem>>>(aat, wo, bo, out);
}

// round 16
// speedup vs baseline: 7.0650x; 1.4588x over previous
#include <cuda_runtime.h>
#include <cuda_fp16.h>
#include <cstdint>

// Problem constants
#define BB 4
#define SS 2048
#define DD 1024
#define HH 16
#define DK 64
#define MM (BB * SS)   // 8192
#define K2 (2 * DD)    // 2048 expanded-K: A' = [Ah | Al] fp16

// ---------------- scratch (device globals; no allocation) ----------------
__device__ __align__(16) __half g_aq[(size_t)MM * K2];   // Q input expanded
__device__ __align__(16) __half g_akv[(size_t)MM * K2];  // K_V input expanded
__device__ __align__(16) __half g_aat[(size_t)MM * K2];  // attn out expanded [oh|ol]
__device__ __align__(16) __half g_wq[DD * DD];           // Wh transposed [n][k]
__device__ __align__(16) __half g_wk[DD * DD];
__device__ __align__(16) __half g_wv[DD * DD];
__device__ __align__(16) __half g_wo[DD * DD];
__device__ __align__(16) __half g_qh[(size_t)MM * DD];   // q hi/lo
__device__ __align__(16) __half g_ql[(size_t)MM * DD];
__device__ __align__(16) __half g_kh[(size_t)MM * DD];   // k single fp16
__device__ __align__(16) __half g_vh[(size_t)MM * DD];   // v single fp16

// ---------------- PTX helpers (sm_103 base target; NO tcgen05) --------
__device__ __forceinline__ uint32_t smem_u32(const void* p) {
    uint32_t a;
    asm("{ .reg .u64 t; cvta.to.shared.u64 t, %1; cvt.u32.u64 %0, t; }" : "=r"(a) : "l"(p));
    return a;
}
__device__ __forceinline__ void cp_async16(uint32_t sm, const void* g) {
    asm volatile("cp.async.cg.shared.global [%0], [%1], 16;" :: "r"(sm), "l"(g));
}
#define CP_COMMIT() asm volatile("cp.async.commit_group;" ::: "memory")
#define CP_WAIT1()  asm volatile("cp.async.wait_group 1;" ::: "memory")

__device__ __forceinline__ void ldsm_x4(uint32_t& r0, uint32_t& r1, uint32_t& r2,
                                        uint32_t& r3, uint32_t addr) {
    asm volatile("ldmatrix.sync.aligned.m8n8.x4.shared.b16 {%0,%1,%2,%3}, [%4];"
                 : "=r"(r0), "=r"(r1), "=r"(r2), "=r"(r3) : "r"(addr));
}
__device__ __forceinline__ void ldsm_x4_t(uint32_t& r0, uint32_t& r1, uint32_t& r2,
                                          uint32_t& r3, uint32_t addr) {
    asm volatile("ldmatrix.sync.aligned.m8n8.x4.trans.shared.b16 {%0,%1,%2,%3}, [%4];"
                 : "=r"(r0), "=r"(r1), "=r"(r2), "=r"(r3) : "r"(addr));
}
__device__ __forceinline__ void mma16816(float* c, uint32_t a0, uint32_t a1,
                                         uint32_t a2, uint32_t a3,
                                         uint32_t b0, uint32_t b1) {
    asm volatile(
        "mma.sync.aligned.m16n8k16.row.col.f32.f16.f16.f32 "
        "{%0,%1,%2,%3}, {%4,%5,%6,%7}, {%8,%9}, {%0,%1,%2,%3};"
        : "+f"(c[0]), "+f"(c[1]), "+f"(c[2]), "+f"(c[3])
        : "r"(a0), "r"(a1), "r"(a2), "r"(a3), "r"(b0), "r"(b1));
}
__device__ __forceinline__ uint32_t sw128(uint32_t off) {
    return off ^ ((off >> 3) & 0x70);
}
__device__ __forceinline__ uint32_t pack_h2(float x, float y) {
    __half2 t = __floats2half2_rn(x, y);
    return *(uint32_t*)&t;
}

// ---------------- conversion kernels ----------------
__global__ void conv_act(const float* __restrict__ src, __half* __restrict__ dst) {
    size_t i = (size_t)blockIdx.x * 256 + threadIdx.x;
    size_t row = i / (DD / 4);
    int c4 = (int)(i % (DD / 4)) * 4;
    float4 x = *(const float4*)(src + row * DD + c4);
    __half2 h0 = __floats2half2_rn(x.x, x.y);
    __half2 h1 = __floats2half2_rn(x.z, x.w);
    __half2 l0 = __floats2half2_rn(x.x - __half2float(h0.x), x.y - __half2float(h0.y));
    __half2 l1 = __floats2half2_rn(x.z - __half2float(h1.x), x.w - __half2float(h1.y));
    size_t b = row * K2;
    *(__half2*)(dst + b + c4)          = h0;
    *(__half2*)(dst + b + c4 + 2)      = h1;
    *(__half2*)(dst + b + DD + c4)     = l0;
    *(__half2*)(dst + b + DD + c4 + 2) = l1;
}

// W [K=1024, N=1024] fp32 -> Wh transposed [n][k] fp16
__global__ void conv_w(const float* __restrict__ W, __half* __restrict__ dst) {
    __shared__ float t[32][33];
    int k0 = blockIdx.x * 32, n0 = blockIdx.y * 32;
    int tx = threadIdx.x, ty = threadIdx.y;  // (32, 8)
#pragma unroll
    for (int r = 0; r < 4; r++)
        t[ty + 8 * r][tx] = W[(size_t)(k0 + ty + 8 * r) * DD + n0 + tx];
    __syncthreads();
#pragma unroll
    for (int r = 0; r < 4; r++)
        dst[(size_t)(n0 + ty + 8 * r) * DD + k0 + tx] = __float2half_rn(t[tx][ty + 8 * r]);
}

// ---------------- HMMA GEMM core: C = A'[MxK2] @ Wh[1024x1024]^T ----------------
// A' = [Ah|Al]; B chunk index = c & 15 (Wh reused for both halves).
#define GSTAGES 3
#define GCHUNKS (K2 / 64)        // 32
#define ATILE_BYTES (128 * 128)  // 16KB
#define STAGE_BYTES (2 * ATILE_BYTES)

struct GemmCore {
    float acc[4][4][4];
    int n0, m0, warp_m, warp_n, lane;
};

__device__ __forceinline__ void gemm_mainloop(
    GemmCore& gc, const __half* __restrict__ A,
    const __half* __restrict__ Bw, char* dsm) {
    const int tid = threadIdx.x;
    const int wid = tid >> 5;
    gc.lane = tid & 31;
    gc.n0 = blockIdx.x * 128; gc.m0 = blockIdx.y * 128;
    gc.warp_m = (wid & 1) * 64;
    gc.warp_n = (wid >> 1) * 32;
    uint32_t base = smem_u32(dsm);
    const int ld_row = tid >> 3, ld_seg = tid & 7;

    auto load_chunk = [&](int c, int s) {
        uint32_t sA = base + s * STAGE_BYTES;
        uint32_t sB = sA + ATILE_BYTES;
        const __half* Ab = A + (size_t)gc.m0 * K2 + c * 64;
        const __half* Bb = Bw + (size_t)gc.n0 * DD + (c & 15) * 64;
#pragma unroll
        for (int p = 0; p < 4; p++) {
            int row = ld_row + 32 * p;
            uint32_t off = sw128((uint32_t)(row * 128 + ld_seg * 16));
            cp_async16(sA + off, Ab + (size_t)row * K2 + ld_seg * 8);
            cp_async16(sB + off, Bb + (size_t)row * DD + ld_seg * 8);
        }
    };

    const uint32_t a_lane = (uint32_t)((gc.lane & 15) * 128 + (gc.lane & 16));
    const uint32_t b_lane = (uint32_t)(((gc.lane & 7) + ((gc.lane & 16) >> 1)) * 128 +
                                       ((gc.lane & 8) << 1));
#pragma unroll
    for (int i = 0; i < 4; i++)
#pragma unroll
        for (int j = 0; j < 4; j++)
#pragma unroll
            for (int e = 0; e < 4; e++) gc.acc[i][j][e] = 0.0f;

    load_chunk(0, 0); CP_COMMIT();
    load_chunk(1, 1); CP_COMMIT();

    for (int c = 0; c < GCHUNKS; c++) {
        const int s = c % GSTAGES;
        CP_WAIT1();
        __syncthreads();
        // issue next-next load AFTER the sync (its stage was read at iter c-1)
        const int cn = c + 2;
        if (cn < GCHUNKS) load_chunk(cn, cn % GSTAGES);
        CP_COMMIT();

        uint32_t sA = base + s * STAGE_BYTES;
        uint32_t sB = sA + ATILE_BYTES;
#pragma unroll
        for (int step = 0; step < 4; step++) {
            const uint32_t kb = step * 32;
            uint32_t af[4][4];
#pragma unroll
            for (int mt = 0; mt < 4; mt++) {
                uint32_t loc = (uint32_t)((gc.warp_m + mt * 16) * 128) + a_lane + kb;
                ldsm_x4(af[mt][0], af[mt][1], af[mt][2], af[mt][3], sA + sw128(loc));
            }
            uint32_t bf[4][2];
#pragma unroll
            for (int bt = 0; bt < 2; bt++) {
                uint32_t loc = (uint32_t)((gc.warp_n + bt * 16) * 128) + b_lane + kb;
                uint32_t r0, r1, r2, r3;
                ldsm_x4(r0, r1, r2, r3, sB + sw128(loc));
                bf[bt * 2 + 0][0] = r0; bf[bt * 2 + 0][1] = r1;
                bf[bt * 2 + 1][0] = r2; bf[bt * 2 + 1][1] = r3;
            }
#pragma unroll
            for (int mt = 0; mt < 4; mt++)
#pragma unroll
                for (int nt = 0; nt < 4; nt++)
                    mma16816(gc.acc[mt][nt], af[mt][0], af[mt][1], af[mt][2], af[mt][3],
                             bf[nt][0], bf[nt][1]);
        }
    }
}

// fp32-output GEMM (final Wo projection)
__global__ __launch_bounds__(256, 2)
void gemm_f32(const __half* __restrict__ A, const __half* __restrict__ Bw,
              const float* __restrict__ bias, float* __restrict__ C) {
    extern __shared__ char dsm[];
    GemmCore gc;
    gemm_mainloop(gc, A, Bw, dsm);
    const int mrow = gc.lane >> 2, ncol = (gc.lane & 3) * 2;
    float2 bv[4];
#pragma unroll
    for (int nt = 0; nt < 4; nt++) {
        int col = gc.n0 + gc.warp_n + nt * 8 + ncol;
        bv[nt].x = __ldg(&bias[col]);
        bv[nt].y = __ldg(&bias[col + 1]);
    }
#pragma unroll
    for (int mt = 0; mt < 4; mt++) {
        const int r0 = gc.m0 + gc.warp_m + mt * 16 + mrow;
#pragma unroll
        for (int nt = 0; nt < 4; nt++) {
            const int col = gc.n0 + gc.warp_n + nt * 8 + ncol;
            float2 o0, o1;
            o0.x = gc.acc[mt][nt][0] + bv[nt].x;
            o0.y = gc.acc[mt][nt][1] + bv[nt].y;
            o1.x = gc.acc[mt][nt][2] + bv[nt].x;
            o1.y = gc.acc[mt][nt][3] + bv[nt].y;
            *(float2*)&C[(size_t)r0 * DD + col] = o0;
            *(float2*)&C[(size_t)(r0 + 8) * DD + col] = o1;
        }
    }
}

// fp16 hi/lo output GEMM (q projection)
__global__ __launch_bounds__(256, 2)
void gemm_hl(const __half* __restrict__ A, const __half* __restrict__ Bw,
             const float* __restrict__ bias, __half* __restrict__ Ch,
             __half* __restrict__ Cl) {
    extern __shared__ char dsm[];
    GemmCore gc;
    gemm_mainloop(gc, A, Bw, dsm);
    const int ncol = (gc.lane & 3) * 2;
    const int mrow = gc.lane >> 2;
    float2 bv[4];
#pragma unroll
    for (int nt = 0; nt < 4; nt++) {
        int col = gc.n0 + gc.warp_n + nt * 8 + ncol;
        bv[nt].x = __ldg(&bias[col]);
        bv[nt].y = __ldg(&bias[col + 1]);
    }
#pragma unroll
    for (int mt = 0; mt < 4; mt++) {
        const int r0 = gc.m0 + gc.warp_m + mt * 16 + mrow;
#pragma unroll
        for (int nt = 0; nt < 4; nt++) {
            const int col = gc.n0 + gc.warp_n + nt * 8 + ncol;
#pragma unroll
            for (int hf = 0; hf < 2; hf++) {
                const int r = r0 + hf * 8;
                float vx = gc.acc[mt][nt][2 * hf + 0] + bv[nt].x;
                float vy = gc.acc[mt][nt][2 * hf + 1] + bv[nt].y;
                __half2 h2 = __floats2half2_rn(vx, vy);
                __half2 l2 = __floats2half2_rn(vx - __half2float(h2.x),
                                               vy - __half2float(h2.y));
                *(__half2*)&Ch[(size_t)r * DD + col] = h2;
                *(__half2*)&Cl[(size_t)r * DD + col] = l2;
            }
        }
    }
}

// fp16 single-output GEMM (k, v projections)
__global__ __launch_bounds__(256, 2)
void gemm_h(const __half* __restrict__ A, const __half* __restrict__ Bw,
            const float* __restrict__ bias, __half* __restrict__ Ch) {
    extern __shared__ char dsm[];
    GemmCore gc;
    gemm_mainloop(gc, A, Bw, dsm);
    const int ncol = (gc.lane & 3) * 2;
    const int mrow = gc.lane >> 2;
    float2 bv[4];
#pragma unroll
    for (int nt = 0; nt < 4; nt++) {
        int col = gc.n0 + gc.warp_n + nt * 8 + ncol;
        bv[nt].x = __ldg(&bias[col]);
        bv[nt].y = __ldg(&bias[col + 1]);
    }
#pragma unroll
    for (int mt = 0; mt < 4; mt++) {
        const int r0 = gc.m0 + gc.warp_m + mt * 16 + mrow;
#pragma unroll
        for (int nt = 0; nt < 4; nt++) {
            const int col = gc.n0 + gc.warp_n + nt * 8 + ncol;
#pragma unroll
            for (int hf = 0; hf < 2; hf++) {
                const int r = r0 + hf * 8;
                __half2 h2 = __floats2half2_rn(gc.acc[mt][nt][2 * hf + 0] + bv[nt].x,
                                               gc.acc[mt][nt][2 * hf + 1] + bv[nt].y);
                *(__half2*)&Ch[(size_t)r * DD + col] = h2;
            }
        }
    }
}

// ---------------- HMMA flash attention (causal, fp16 2-term) ----------------
// CTA: 128 q rows, 8 warps. KV tiles 64, 3-stage pipeline (kh+vh = 16KB/stage).
// Smem: qh 16KB + ql 16KB + 3x16KB = 80KB.
#define FQ_BYTES 16384
#define FST_BYTES 16384
#define F_STAGES 3

__global__ __launch_bounds__(256, 2)
void flash_hmma(const __half* __restrict__ Qh, const __half* __restrict__ Ql,
                const __half* __restrict__ Kh, const __half* __restrict__ Vh,
                __half* __restrict__ aat) {
    const int qi = (int)(gridDim.x - 1) - (int)blockIdx.x;  // heavy CTAs first
    const int bh = blockIdx.y;
    const int b = bh >> 4, h = bh & 15;
    const int tid = threadIdx.x;
    const int w = tid >> 5, lane = tid & 31;

    extern __shared__ char dsm[];
    uint32_t sqh = (smem_u32(dsm) + 1023) & ~1023u;
    uint32_t sql = sqh + FQ_BYTES;
    uint32_t skv = sql + FQ_BYTES;

    const size_t rowbase = (size_t)b * SS;
    const int colh = h * 64;

    // q hi/lo tiles (128 rows x 64 fp16 = 128B rows)
    {
        int row = tid >> 1;
        int s0 = (tid & 1) * 4;
        const __half* srcH = Qh + (rowbase + (size_t)qi * 128 + row) * DD + colh;
        const __half* srcL = Ql + (rowbase + (size_t)qi * 128 + row) * DD + colh;
#pragma unroll
        for (int s = 0; s < 4; s++) {
            uint32_t off = sw128((uint32_t)(row * 128 + (s0 + s) * 16));
            cp_async16(sqh + off, srcH + (s0 + s) * 8);
            cp_async16(sql + off, srcL + (s0 + s) * 8);
        }
    }
    CP_COMMIT();

    const int nt_kv = 2 * qi + 2;
    auto load_kv = [&](int kt, int st) {
        uint32_t sb = skv + st * FST_BYTES;
        int row = tid >> 2, sg = tid & 3;
        size_t grow = (rowbase + (size_t)kt * 64 + row) * DD + colh;
#pragma unroll
        for (int j = 0; j < 2; j++) {
            int seg = sg + j * 4;
            uint32_t off = sw128((uint32_t)(row * 128 + seg * 16));
            cp_async16(sb + off, Kh + grow + seg * 8);
            cp_async16(sb + 8192 + off, Vh + grow + seg * 8);
        }
    };
    load_kv(0, 0); CP_COMMIT();
    load_kv(1, 1); CP_COMMIT();

    const uint32_t a_lane = (uint32_t)((lane & 15) * 128 + (lane & 16));
    const uint32_t b_lane = (uint32_t)(((lane & 7) + ((lane & 16) >> 1)) * 128 +
                                       ((lane & 8) << 1));
    const uint32_t v_lane = (uint32_t)((lane & 15) * 128 + (lane & 16));

    // wait for q (2 kv groups pending), then hoist qh fragments to registers
    asm volatile("cp.async.wait_group 2;" ::: "memory");
    __syncthreads();
    uint32_t qhf[4][4];
#pragma unroll
    for (int c = 0; c < 4; c++) {
        uint32_t loc = (uint32_t)(w * 16 * 128) + a_lane + c * 32;
        ldsm_x4(qhf[c][0], qhf[c][1], qhf[c][2], qhf[c][3], sqh + sw128(loc));
    }

    float O[8][4];
#pragma unroll
    for (int nt = 0; nt < 8; nt++)
#pragma unroll
        for (int e = 0; e < 4; e++) O[nt][e] = 0.0f;
    float mA = -INFINITY, mB = -INFINITY, lA = 0.0f, lB = 0.0f;

    for (int kt = 0; kt < nt_kv; kt++) {
        CP_WAIT1();
        __syncthreads();
        if (kt + 2 < nt_kv) load_kv(kt + 2, (kt + 2) % F_STAGES);
        CP_COMMIT();

        uint32_t sKH = skv + (kt % F_STAGES) * FST_BYTES;
        uint32_t sVH = sKH + 8192;

        // ---- S = (qh+ql)·kh ----
        float S[8][4];
#pragma unroll
        for (int nt = 0; nt < 8; nt++)
#pragma unroll
            for (int e = 0; e < 4; e++) S[nt][e] = 0.0f;

#pragma unroll
        for (int c = 0; c < 4; c++) {
            uint32_t aloc = (uint32_t)(w * 16 * 128) + a_lane + c * 32;
            uint32_t qlf[4];
            ldsm_x4(qlf[0], qlf[1], qlf[2], qlf[3], sql + sw128(aloc));
#pragma unroll
            for (int nt2 = 0; nt2 < 4; nt2++) {
                uint32_t loc = (uint32_t)(nt2 * 16 * 128) + b_lane + c * 32;
                uint32_t h0, h1, h2, h3;
                ldsm_x4(h0, h1, h2, h3, sKH + sw128(loc));
                mma16816(S[2 * nt2 + 0], qhf[c][0], qhf[c][1], qhf[c][2], qhf[c][3], h0, h1);
                mma16816(S[2 * nt2 + 1], qhf[c][0], qhf[c][1], qhf[c][2], qhf[c][3], h2, h3);
                mma16816(S[2 * nt2 + 0], qlf[0], qlf[1], qlf[2], qlf[3], h0, h1);
                mma16816(S[2 * nt2 + 1], qlf[0], qlf[1], qlf[2], qlf[3], h2, h3);
            }
        }

        // scale 1/sqrt(dk) in fp32, then causal mask
#pragma unroll
        for (int nt = 0; nt < 8; nt++)
#pragma unroll
            for (int e = 0; e < 4; e++) S[nt][e] *= 0.125f;

        if (kt >= 2 * qi) {
            const int row0 = qi * 128 + w * 16 + (lane >> 2);
            const int col0 = kt * 64 + 2 * (lane & 3);
#pragma unroll
            for (int nt = 0; nt < 8; nt++)
#pragma unroll
                for (int e = 0; e < 2; e++) {
                    int col = col0 + nt * 8 + e;
                    if (col > row0) S[nt][e] = -1e30f;
                    if (col > row0 + 8) S[nt][2 + e] = -1e30f;
                }
        }

        // ---- online softmax (rows rA=lane/4, rB=rA+8 per warp) ----
        float tmA = -INFINITY, tmB = -INFINITY;
#pragma unroll
        for (int nt = 0; nt < 8; nt++) {
            tmA = fmaxf(tmA, fmaxf(S[nt][0], S[nt][1]));
            tmB = fmaxf(tmB, fmaxf(S[nt][2], S[nt][3]));
        }
        tmA = fmaxf(tmA, __shfl_xor_sync(0xffffffffu, tmA, 1));
        tmA = fmaxf(tmA, __shfl_xor_sync(0xffffffffu, tmA, 2));
        tmB = fmaxf(tmB, __shfl_xor_sync(0xffffffffu, tmB, 1));
        tmB = fmaxf(tmB, __shfl_xor_sync(0xffffffffu, tmB, 2));

        float mnA = fmaxf(mA, tmA), mnB = fmaxf(mB, tmB);
        float alA = __expf(mA - mnA), alB = __expf(mB - mnB);
        mA = mnA; mB = mnB;

        float rsA = 0.0f, rsB = 0.0f;
#pragma unroll
        for (int nt = 0; nt < 8; nt++) {
            S[nt][0] = __expf(S[nt][0] - mnA); rsA += S[nt][0];
            S[nt][1] = __expf(S[nt][1] - mnA); rsA += S[nt][1];
            S[nt][2] = __expf(S[nt][2] - mnB); rsB += S[nt][2];
            S[nt][3] = __expf(S[nt][3] - mnB); rsB += S[nt][3];
        }
        rsA += __shfl_xor_sync(0xffffffffu, rsA, 1);
        rsA += __shfl_xor_sync(0xffffffffu, rsA, 2);
        rsB += __shfl_xor_sync(0xffffffffu, rsB, 1);
        rsB += __shfl_xor_sync(0xffffffffu, rsB, 2);
        lA = lA * alA + rsA;
        lB = lB * alB + rsB;
#pragma unroll
        for (int nt = 0; nt < 8; nt++) {
            O[nt][0] *= alA; O[nt][1] *= alA;
            O[nt][2] *= alB; O[nt][3] *= alB;
        }

        // ---- O += (ph+pl)·vh ----
#pragma unroll
        for (int c = 0; c < 4; c++) {
            uint32_t ph[4], pl[4];
#pragma unroll
            for (int half_ = 0; half_ < 2; half_++) {
                const float s0 = S[2 * c + half_][0], s1 = S[2 * c + half_][1];
                const float s2 = S[2 * c + half_][2], s3 = S[2 * c + half_][3];
                uint32_t h01 = pack_h2(s0, s1);
                uint32_t h23 = pack_h2(s2, s3);
                __half2 hb01 = *(__half2*)&h01;
                __half2 hb23 = *(__half2*)&h23;
                uint32_t l01 = pack_h2(s0 - __half2float(hb01.x),
                                       s1 - __half2float(hb01.y));
                uint32_t l23 = pack_h2(s2 - __half2float(hb23.x),
                                       s3 - __half2float(hb23.y));
                ph[2 * half_ + 0] = h01; ph[2 * half_ + 1] = h23;
                pl[2 * half_ + 0] = l01; pl[2 * half_ + 1] = l23;
            }
#pragma unroll
            for (int nt2 = 0; nt2 < 4; nt2++) {
                uint32_t loc = (uint32_t)(c * 16 * 128 + nt2 * 32) + v_lane;
                uint32_t he0, he1, ho0, ho1;
                ldsm_x4_t(he0, he1, ho0, ho1, sVH + sw128(loc));
                mma16816(O[2 * nt2 + 0], ph[0], ph[1], ph[2], ph[3], he0, he1);
                mma16816(O[2 * nt2 + 1], ph[0], ph[1], ph[2], ph[3], ho0, ho1);
                mma16816(O[2 * nt2 + 0], pl[0], pl[1], pl[2], pl[3], he0, he1);
                mma16816(O[2 * nt2 + 1], pl[0], pl[1], pl[2], pl[3], ho0, ho1);
            }
        }
    }

    // ---- epilogue: normalize, write [oh | ol] into aat (K2 layout) ----
    const float invA = 1.0f / lA, invB = 1.0f / lB;
    const int rA = b * SS + qi * 128 + w * 16 + (lane >> 2);
    const int rB = rA + 8;
    const int cb = colh + 2 * (lane & 3);
#pragma unroll
    for (int nt = 0; nt < 8; nt++) {
        const int col = cb + nt * 8;
        {
            float vx = O[nt][0] * invA, vy = O[nt][1] * invA;
            __half2 h2 = __floats2half2_rn(vx, vy);
            __half2 l2 = __floats2half2_rn(vx - __half2float(h2.x),
                                           vy - __half2float(h2.y));
            __half* base = aat + (size_t)rA * K2;
            *(__half2*)(base + col) = h2;
            *(__half2*)(base + DD + col) = l2;
        }
        {
            float vx = O[nt][2] * invB, vy = O[nt][3] * invB;
            __half2 h2 = __floats2half2_rn(vx, vy);
            __half2 l2 = __floats2half2_rn(vx - __half2float(h2.x),
                                           vy - __half2float(h2.y));
            __half* base = aat + (size_t)rB * K2;
            *(__half2*)(base + col) = h2;
            *(__half2*)(base + DD + col) = l2;
        }
    }
}

// ---------------- launch ----------------
extern "C" void kernel_launch(void* const* d_in, const int* in_sizes, int n_in,
                              void* d_out, int out_size) {
    const float* Q   = (const float*)d_in[0];
    const float* K_V = (const float*)d_in[1];
    const float* Wq = (const float*)d_in[3];
    const float* bq = (const float*)d_in[4];
    const float* Wk = (const float*)d_in[5];
    const float* bk = (const float*)d_in[6];
    const float* Wv = (const float*)d_in[7];
    const float* bv = (const float*)d_in[8];
    const float* Wo = (const float*)d_in[9];
    const float* bo = (const float*)d_in[10];
    float* out = (float*)d_out;

    __half *aq, *akv, *aat, *wq, *wk, *wv, *wo, *qh, *ql, *kh, *vh;
    cudaGetSymbolAddress((void**)&aq, g_aq);
    cudaGetSymbolAddress((void**)&akv, g_akv);
    cudaGetSymbolAddress((void**)&aat, g_aat);
    cudaGetSymbolAddress((void**)&wq, g_wq);
    cudaGetSymbolAddress((void**)&wk, g_wk);
    cudaGetSymbolAddress((void**)&wv, g_wv);
    cudaGetSymbolAddress((void**)&wo, g_wo);
    cudaGetSymbolAddress((void**)&qh, g_qh);
    cudaGetSymbolAddress((void**)&ql, g_ql);
    cudaGetSymbolAddress((void**)&kh, g_kh);
    cudaGetSymbolAddress((void**)&vh, g_vh);

    const int gsmem = GSTAGES * STAGE_BYTES;  // 96KB
    cudaFuncSetAttribute(gemm_f32, cudaFuncAttributeMaxDynamicSharedMemorySize, gsmem);
    cudaFuncSetAttribute(gemm_hl, cudaFuncAttributeMaxDynamicSharedMemorySize, gsmem);
    cudaFuncSetAttribute(gemm_h, cudaFuncAttributeMaxDynamicSharedMemorySize, gsmem);
    const int fsmem = 2 * FQ_BYTES + F_STAGES * FST_BYTES + 1024;  // ~81KB
    cudaFuncSetAttribute(flash_hmma, cudaFuncAttributeMaxDynamicSharedMemorySize, fsmem);

    // conversions
    dim3 wgrid(32, 32), wblk(32, 8);
    conv_w<<<wgrid, wblk>>>(Wq, wq);
    conv_w<<<wgrid, wblk>>>(Wk, wk);
    conv_w<<<wgrid, wblk>>>(Wv, wv);
    conv_w<<<wgrid, wblk>>>(Wo, wo);
    conv_act<<<MM * DD / 4 / 256, 256>>>(Q, aq);
    conv_act<<<MM * DD / 4 / 256, 256>>>(K_V, akv);

    // projections (fp16 2-term)
    dim3 gg(DD / 128, MM / 128);
    gemm_hl<<<gg, 256, gsmem>>>(aq,  wq, bq, qh, ql);
    gemm_h <<<gg, 256, gsmem>>>(akv, wk, bk, kh);
    gemm_h <<<gg, 256, gsmem>>>(akv, wv, bv, vh);

    // flash attention -> expanded aat [oh|ol]
    flash_hmma<<<dim3(SS / 128, BB * HH), 256, fsmem>>>(qh, ql, kh, vh, aat);

    // output projection (fp32 out)
    gemm_f32<<<gg, 256, gsmem>>>(aat, wo, bo, out);
}

// round 17
// speedup vs baseline: 12.3533x; 1.7485x over previous
#include <cuda_runtime.h>
#include <cuda_fp16.h>
#include <cstdint>

// Problem constants
#define BB 4
#define SS 2048
#define DD 1024
#define HH 16
#define DK 64
#define MM (BB * SS)   // 8192

// ---------------- scratch (device globals; no allocation) ----------------
__device__ __align__(16) __half g_aq[(size_t)MM * DD];   // Q fp16
__device__ __align__(16) __half g_akv[(size_t)MM * DD];  // K_V fp16
__device__ __align__(16) __half g_aat[(size_t)MM * DD];  // attn out fp16
__device__ __align__(16) __half g_wq[DD * DD];           // W transposed [n][k] fp16
__device__ __align__(16) __half g_wk[DD * DD];
__device__ __align__(16) __half g_wv[DD * DD];
__device__ __align__(16) __half g_wo[DD * DD];
__device__ __align__(16) __half g_qh[(size_t)MM * DD];
__device__ __align__(16) __half g_kh[(size_t)MM * DD];
__device__ __align__(16) __half g_vh[(size_t)MM * DD];

// ---------------- PTX helpers (sm_103 base target; NO tcgen05) --------
__device__ __forceinline__ uint32_t smem_u32(const void* p) {
    uint32_t a;
    asm("{ .reg .u64 t; cvta.to.shared.u64 t, %1; cvt.u32.u64 %0, t; }" : "=r"(a) : "l"(p));
    return a;
}
__device__ __forceinline__ void cp_async16(uint32_t sm, const void* g) {
    asm volatile("cp.async.cg.shared.global [%0], [%1], 16;" :: "r"(sm), "l"(g));
}
#define CP_COMMIT() asm volatile("cp.async.commit_group;" ::: "memory")
#define CP_WAIT1()  asm volatile("cp.async.wait_group 1;" ::: "memory")

__device__ __forceinline__ void ldsm_x4(uint32_t& r0, uint32_t& r1, uint32_t& r2,
                                        uint32_t& r3, uint32_t addr) {
    asm volatile("ldmatrix.sync.aligned.m8n8.x4.shared.b16 {%0,%1,%2,%3}, [%4];"
                 : "=r"(r0), "=r"(r1), "=r"(r2), "=r"(r3) : "r"(addr));
}
__device__ __forceinline__ void ldsm_x4_t(uint32_t& r0, uint32_t& r1, uint32_t& r2,
                                          uint32_t& r3, uint32_t addr) {
    asm volatile("ldmatrix.sync.aligned.m8n8.x4.trans.shared.b16 {%0,%1,%2,%3}, [%4];"
                 : "=r"(r0), "=r"(r1), "=r"(r2), "=r"(r3) : "r"(addr));
}
__device__ __forceinline__ void mma16816(float* c, uint32_t a0, uint32_t a1,
                                         uint32_t a2, uint32_t a3,
                                         uint32_t b0, uint32_t b1) {
    asm volatile(
        "mma.sync.aligned.m16n8k16.row.col.f32.f16.f16.f32 "
        "{%0,%1,%2,%3}, {%4,%5,%6,%7}, {%8,%9}, {%0,%1,%2,%3};"
        : "+f"(c[0]), "+f"(c[1]), "+f"(c[2]), "+f"(c[3])
        : "r"(a0), "r"(a1), "r"(a2), "r"(a3), "r"(b0), "r"(b1));
}
__device__ __forceinline__ uint32_t sw128(uint32_t off) {
    return off ^ ((off >> 3) & 0x70);
}
__device__ __forceinline__ uint32_t pack_h2(float x, float y) {
    __half2 t = __floats2half2_rn(x, y);
    return *(uint32_t*)&t;
}

// ---------------- conversion kernels (batched) ----------------
// elementwise fp32 -> fp16, 8 elems/thread; blockIdx.y selects (src,dst)
__global__ void conv_act_all(const float* __restrict__ s0, __half* __restrict__ d0,
                             const float* __restrict__ s1, __half* __restrict__ d1) {
    const float* src = blockIdx.y ? s1 : s0;
    __half* dst = blockIdx.y ? d1 : d0;
    size_t i = ((size_t)blockIdx.x * 256 + threadIdx.x) * 8;
    float4 a = *(const float4*)(src + i);
    float4 b = *(const float4*)(src + i + 4);
    __half2 o[4];
    o[0] = __floats2half2_rn(a.x, a.y);
    o[1] = __floats2half2_rn(a.z, a.w);
    o[2] = __floats2half2_rn(b.x, b.y);
    o[3] = __floats2half2_rn(b.z, b.w);
    *(uint4*)(dst + i) = *(uint4*)o;
}

// W [K=1024, N=1024] fp32 -> fp16 transposed [n][k]; blockIdx.z selects weight
__global__ void conv_w_all(const float* __restrict__ W0, __half* __restrict__ D0,
                           const float* __restrict__ W1, __half* __restrict__ D1,
                           const float* __restrict__ W2, __half* __restrict__ D2,
                           const float* __restrict__ W3, __half* __restrict__ D3) {
    const float* W; __half* dst;
    switch (blockIdx.z) {
        case 0: W = W0; dst = D0; break;
        case 1: W = W1; dst = D1; break;
        case 2: W = W2; dst = D2; break;
        default: W = W3; dst = D3; break;
    }
    __shared__ float t[32][33];
    int k0 = blockIdx.x * 32, n0 = blockIdx.y * 32;
    int tx = threadIdx.x, ty = threadIdx.y;  // (32, 8)
#pragma unroll
    for (int r = 0; r < 4; r++)
        t[ty + 8 * r][tx] = W[(size_t)(k0 + ty + 8 * r) * DD + n0 + tx];
    __syncthreads();
#pragma unroll
    for (int r = 0; r < 4; r++)
        dst[(size_t)(n0 + ty + 8 * r) * DD + k0 + tx] = __float2half_rn(t[tx][ty + 8 * r]);
}

// ---------------- HMMA GEMM core: C = A[Mx1024] @ W[1024x1024]^T ----------------
#define KDIM 1024
#define GSTAGES 3
#define GCHUNKS (KDIM / 64)      // 16
#define ATILE_BYTES (128 * 128)  // 16KB
#define STAGE_BYTES (2 * ATILE_BYTES)

struct GemmCore {
    float acc[4][4][4];
    int n0, m0, warp_m, warp_n, lane;
};

__device__ __forceinline__ void gemm_mainloop(
    GemmCore& gc, const __half* __restrict__ A,
    const __half* __restrict__ Bw, char* dsm) {
    const int tid = threadIdx.x;
    const int wid = tid >> 5;
    gc.lane = tid & 31;
    gc.n0 = blockIdx.x * 128; gc.m0 = blockIdx.y * 128;
    gc.warp_m = (wid & 1) * 64;
    gc.warp_n = (wid >> 1) * 32;
    uint32_t base = smem_u32(dsm);
    const int ld_row = tid >> 3, ld_seg = tid & 7;

    auto load_chunk = [&](int c, int s) {
        uint32_t sA = base + s * STAGE_BYTES;
        uint32_t sB = sA + ATILE_BYTES;
        const __half* Ab = A + (size_t)gc.m0 * KDIM + c * 64;
        const __half* Bb = Bw + (size_t)gc.n0 * KDIM + c * 64;
#pragma unroll
        for (int p = 0; p < 4; p++) {
            int row = ld_row + 32 * p;
            uint32_t off = sw128((uint32_t)(row * 128 + ld_seg * 16));
            cp_async16(sA + off, Ab + (size_t)row * KDIM + ld_seg * 8);
            cp_async16(sB + off, Bb + (size_t)row * KDIM + ld_seg * 8);
        }
    };

    const uint32_t a_lane = (uint32_t)((gc.lane & 15) * 128 + (gc.lane & 16));
    const uint32_t b_lane = (uint32_t)(((gc.lane & 7) + ((gc.lane & 16) >> 1)) * 128 +
                                       ((gc.lane & 8) << 1));
#pragma unroll
    for (int i = 0; i < 4; i++)
#pragma unroll
        for (int j = 0; j < 4; j++)
#pragma unroll
            for (int e = 0; e < 4; e++) gc.acc[i][j][e] = 0.0f;

    load_chunk(0, 0); CP_COMMIT();
    load_chunk(1, 1); CP_COMMIT();

    for (int c = 0; c < GCHUNKS; c++) {
        const int s = c % GSTAGES;
        CP_WAIT1();
        __syncthreads();
        const int cn = c + 2;
        if (cn < GCHUNKS) load_chunk(cn, cn % GSTAGES);
        CP_COMMIT();

        uint32_t sA = base + s * STAGE_BYTES;
        uint32_t sB = sA + ATILE_BYTES;
#pragma unroll
        for (int step = 0; step < 4; step++) {
            const uint32_t kb = step * 32;
            uint32_t af[4][4];
#pragma unroll
            for (int mt = 0; mt < 4; mt++) {
                uint32_t loc = (uint32_t)((gc.warp_m + mt * 16) * 128) + a_lane + kb;
                ldsm_x4(af[mt][0], af[mt][1], af[mt][2], af[mt][3], sA + sw128(loc));
            }
            uint32_t bf[4][2];
#pragma unroll
            for (int bt = 0; bt < 2; bt++) {
                uint32_t loc = (uint32_t)((gc.warp_n + bt * 16) * 128) + b_lane + kb;
                uint32_t r0, r1, r2, r3;
                ldsm_x4(r0, r1, r2, r3, sB + sw128(loc));
                bf[bt * 2 + 0][0] = r0; bf[bt * 2 + 0][1] = r1;
                bf[bt * 2 + 1][0] = r2; bf[bt * 2 + 1][1] = r3;
            }
#pragma unroll
            for (int mt = 0; mt < 4; mt++)
#pragma unroll
                for (int nt = 0; nt < 4; nt++)
                    mma16816(gc.acc[mt][nt], af[mt][0], af[mt][1], af[mt][2], af[mt][3],
                             bf[nt][0], bf[nt][1]);
        }
    }
}

// fp32-output GEMM (final Wo projection)
__global__ __launch_bounds__(256, 2)
void gemm_f32(const __half* __restrict__ A, const __half* __restrict__ Bw,
              const float* __restrict__ bias, float* __restrict__ C) {
    extern __shared__ char dsm[];
    GemmCore gc;
    gemm_mainloop(gc, A, Bw, dsm);
    const int mrow = gc.lane >> 2, ncol = (gc.lane & 3) * 2;
    float2 bv[4];
#pragma unroll
    for (int nt = 0; nt < 4; nt++) {
        int col = gc.n0 + gc.warp_n + nt * 8 + ncol;
        bv[nt].x = __ldg(&bias[col]);
        bv[nt].y = __ldg(&bias[col + 1]);
    }
#pragma unroll
    for (int mt = 0; mt < 4; mt++) {
        const int r0 = gc.m0 + gc.warp_m + mt * 16 + mrow;
#pragma unroll
        for (int nt = 0; nt < 4; nt++) {
            const int col = gc.n0 + gc.warp_n + nt * 8 + ncol;
            float2 o0, o1;
            o0.x = gc.acc[mt][nt][0] + bv[nt].x;
            o0.y = gc.acc[mt][nt][1] + bv[nt].y;
            o1.x = gc.acc[mt][nt][2] + bv[nt].x;
            o1.y = gc.acc[mt][nt][3] + bv[nt].y;
            *(float2*)&C[(size_t)r0 * DD + col] = o0;
            *(float2*)&C[(size_t)(r0 + 8) * DD + col] = o1;
        }
    }
}

// fp16-output GEMM (q, k, v projections)
__global__ __launch_bounds__(256, 2)
void gemm_h(const __half* __restrict__ A, const __half* __restrict__ Bw,
            const float* __restrict__ bias, __half* __restrict__ Ch) {
    extern __shared__ char dsm[];
    GemmCore gc;
    gemm_mainloop(gc, A, Bw, dsm);
    const int ncol = (gc.lane & 3) * 2;
    const int mrow = gc.lane >> 2;
    float2 bv[4];
#pragma unroll
    for (int nt = 0; nt < 4; nt++) {
        int col = gc.n0 + gc.warp_n + nt * 8 + ncol;
        bv[nt].x = __ldg(&bias[col]);
        bv[nt].y = __ldg(&bias[col + 1]);
    }
#pragma unroll
    for (int mt = 0; mt < 4; mt++) {
        const int r0 = gc.m0 + gc.warp_m + mt * 16 + mrow;
#pragma unroll
        for (int nt = 0; nt < 4; nt++) {
            const int col = gc.n0 + gc.warp_n + nt * 8 + ncol;
#pragma unroll
            for (int hf = 0; hf < 2; hf++) {
                const int r = r0 + hf * 8;
                __half2 h2 = __floats2half2_rn(gc.acc[mt][nt][2 * hf + 0] + bv[nt].x,
                                               gc.acc[mt][nt][2 * hf + 1] + bv[nt].y);
                *(__half2*)&Ch[(size_t)r * DD + col] = h2;
            }
        }
    }
}

// ---------------- HMMA flash attention (causal, plain fp16) ----------------
// CTA: 128 q rows, 8 warps (m16). KV tiles 64, 3-stage pipeline (kh+vh=16KB/stage).
// Smem: q 16KB + 3x16KB = 64KB.
#define FQ_BYTES 16384
#define FST_BYTES 16384
#define F_STAGES 3

__global__ __launch_bounds__(256, 2)
void flash_hmma(const __half* __restrict__ Qh, const __half* __restrict__ Kh,
                const __half* __restrict__ Vh, __half* __restrict__ aat) {
    const int qi = (int)(gridDim.x - 1) - (int)blockIdx.x;  // heavy CTAs first
    const int bh = blockIdx.y;
    const int b = bh >> 4, h = bh & 15;
    const int tid = threadIdx.x;
    const int w = tid >> 5, lane = tid & 31;

    extern __shared__ char dsm[];
    uint32_t sqh = (smem_u32(dsm) + 1023) & ~1023u;
    uint32_t skv = sqh + FQ_BYTES;

    const size_t rowbase = (size_t)b * SS;
    const int colh = h * 64;

    // q tile (128 rows x 64 fp16 = 128B rows)
    {
        int row = tid >> 1;
        int s0 = (tid & 1) * 4;
        const __half* srcH = Qh + (rowbase + (size_t)qi * 128 + row) * DD + colh;
#pragma unroll
        for (int s = 0; s < 4; s++) {
            uint32_t off = sw128((uint32_t)(row * 128 + (s0 + s) * 16));
            cp_async16(sqh + off, srcH + (s0 + s) * 8);
        }
    }
    CP_COMMIT();

    const int nt_kv = 2 * qi + 2;
    auto load_kv = [&](int kt, int st) {
        uint32_t sb = skv + st * FST_BYTES;
        int row = tid >> 2, sg = tid & 3;
        size_t grow = (rowbase + (size_t)kt * 64 + row) * DD + colh;
#pragma unroll
        for (int j = 0; j < 2; j++) {
            int seg = sg + j * 4;
            uint32_t off = sw128((uint32_t)(row * 128 + seg * 16));
            cp_async16(sb + off, Kh + grow + seg * 8);
            cp_async16(sb + 8192 + off, Vh + grow + seg * 8);
        }
    };
    load_kv(0, 0); CP_COMMIT();
    load_kv(1, 1); CP_COMMIT();

    const uint32_t a_lane = (uint32_t)((lane & 15) * 128 + (lane & 16));
    const uint32_t b_lane = (uint32_t)(((lane & 7) + ((lane & 16) >> 1)) * 128 +
                                       ((lane & 8) << 1));
    const uint32_t v_lane = (uint32_t)((lane & 15) * 128 + (lane & 16));

    // wait for q (2 kv groups still pending), hoist q fragments to registers
    asm volatile("cp.async.wait_group 2;" ::: "memory");
    __syncthreads();
    uint32_t qhf[4][4];
#pragma unroll
    for (int c = 0; c < 4; c++) {
        uint32_t loc = (uint32_t)(w * 16 * 128) + a_lane + c * 32;
        ldsm_x4(qhf[c][0], qhf[c][1], qhf[c][2], qhf[c][3], sqh + sw128(loc));
    }

    float O[8][4];
#pragma unroll
    for (int nt = 0; nt < 8; nt++)
#pragma unroll
        for (int e = 0; e < 4; e++) O[nt][e] = 0.0f;
    float mA = -INFINITY, mB = -INFINITY, lA = 0.0f, lB = 0.0f;

    for (int kt = 0; kt < nt_kv; kt++) {
        CP_WAIT1();
        __syncthreads();
        if (kt + 2 < nt_kv) load_kv(kt + 2, (kt + 2) % F_STAGES);
        CP_COMMIT();

        uint32_t sKH = skv + (kt % F_STAGES) * FST_BYTES;
        uint32_t sVH = sKH + 8192;

        // ---- S = q·kᵀ ----
        float S[8][4];
#pragma unroll
        for (int nt = 0; nt < 8; nt++)
#pragma unroll
            for (int e = 0; e < 4; e++) S[nt][e] = 0.0f;

#pragma unroll
        for (int c = 0; c < 4; c++) {
#pragma unroll
            for (int nt2 = 0; nt2 < 4; nt2++) {
                uint32_t loc = (uint32_t)(nt2 * 16 * 128) + b_lane + c * 32;
                uint32_t h0, h1, h2, h3;
                ldsm_x4(h0, h1, h2, h3, sKH + sw128(loc));
                mma16816(S[2 * nt2 + 0], qhf[c][0], qhf[c][1], qhf[c][2], qhf[c][3], h0, h1);
                mma16816(S[2 * nt2 + 1], qhf[c][0], qhf[c][1], qhf[c][2], qhf[c][3], h2, h3);
            }
        }

        // scale 1/sqrt(dk) in fp32, then causal mask
#pragma unroll
        for (int nt = 0; nt < 8; nt++)
#pragma unroll
            for (int e = 0; e < 4; e++) S[nt][e] *= 0.125f;

        if (kt >= 2 * qi) {
            const int row0 = qi * 128 + w * 16 + (lane >> 2);
            const int col0 = kt * 64 + 2 * (lane & 3);
#pragma unroll
            for (int nt = 0; nt < 8; nt++)
#pragma unroll
                for (int e = 0; e < 2; e++) {
                    int col = col0 + nt * 8 + e;
                    if (col > row0) S[nt][e] = -1e30f;
                    if (col > row0 + 8) S[nt][2 + e] = -1e30f;
                }
        }

        // ---- online softmax (rows rA=lane/4, rB=rA+8 per warp) ----
        float tmA = -INFINITY, tmB = -INFINITY;
#pragma unroll
        for (int nt = 0; nt < 8; nt++) {
            tmA = fmaxf(tmA, fmaxf(S[nt][0], S[nt][1]));
            tmB = fmaxf(tmB, fmaxf(S[nt][2], S[nt][3]));
        }
        tmA = fmaxf(tmA, __shfl_xor_sync(0xffffffffu, tmA, 1));
        tmA = fmaxf(tmA, __shfl_xor_sync(0xffffffffu, tmA, 2));
        tmB = fmaxf(tmB, __shfl_xor_sync(0xffffffffu, tmB, 1));
        tmB = fmaxf(tmB, __shfl_xor_sync(0xffffffffu, tmB, 2));

        float mnA = fmaxf(mA, tmA), mnB = fmaxf(mB, tmB);
        float alA = __expf(mA - mnA), alB = __expf(mB - mnB);
        mA = mnA; mB = mnB;

        float rsA = 0.0f, rsB = 0.0f;
#pragma unroll
        for (int nt = 0; nt < 8; nt++) {
            S[nt][0] = __expf(S[nt][0] - mnA); rsA += S[nt][0];
            S[nt][1] = __expf(S[nt][1] - mnA); rsA += S[nt][1];
            S[nt][2] = __expf(S[nt][2] - mnB); rsB += S[nt][2];
            S[nt][3] = __expf(S[nt][3] - mnB); rsB += S[nt][3];
        }
        rsA += __shfl_xor_sync(0xffffffffu, rsA, 1);
        rsA += __shfl_xor_sync(0xffffffffu, rsA, 2);
        rsB += __shfl_xor_sync(0xffffffffu, rsB, 1);
        rsB += __shfl_xor_sync(0xffffffffu, rsB, 2);
        lA = lA * alA + rsA;
        lB = lB * alB + rsB;
#pragma unroll
        for (int nt = 0; nt < 8; nt++) {
            O[nt][0] *= alA; O[nt][1] *= alA;
            O[nt][2] *= alB; O[nt][3] *= alB;
        }

        // ---- O += P·V ----
#pragma unroll
        for (int c = 0; c < 4; c++) {
            uint32_t ph[4];
#pragma unroll
            for (int half_ = 0; half_ < 2; half_++) {
                ph[2 * half_ + 0] = pack_h2(S[2 * c + half_][0], S[2 * c + half_][1]);
                ph[2 * half_ + 1] = pack_h2(S[2 * c + half_][2], S[2 * c + half_][3]);
            }
#pragma unroll
            for (int nt2 = 0; nt2 < 4; nt2++) {
                uint32_t loc = (uint32_t)(c * 16 * 128 + nt2 * 32) + v_lane;
                uint32_t he0, he1, ho0, ho1;
                ldsm_x4_t(he0, he1, ho0, ho1, sVH + sw128(loc));
                mma16816(O[2 * nt2 + 0], ph[0], ph[1], ph[2], ph[3], he0, he1);
                mma16816(O[2 * nt2 + 1], ph[0], ph[1], ph[2], ph[3], ho0, ho1);
            }
        }
    }

    // ---- epilogue: normalize, write fp16 into aat ----
    const float invA = 1.0f / lA, invB = 1.0f / lB;
    const int rA = b * SS + qi * 128 + w * 16 + (lane >> 2);
    const int rB = rA + 8;
    const int cb = colh + 2 * (lane & 3);
#pragma unroll
    for (int nt = 0; nt < 8; nt++) {
        const int col = cb + nt * 8;
        *(__half2*)(aat + (size_t)rA * DD + col) =
            __floats2half2_rn(O[nt][0] * invA, O[nt][1] * invA);
        *(__half2*)(aat + (size_t)rB * DD + col) =
            __floats2half2_rn(O[nt][2] * invB, O[nt][3] * invB);
    }
}

// ---------------- launch ----------------
extern "C" void kernel_launch(void* const* d_in, const int* in_sizes, int n_in,
                              void* d_out, int out_size) {
    const float* Q   = (const float*)d_in[0];
    const float* K_V = (const float*)d_in[1];
    const float* Wq = (const float*)d_in[3];
    const float* bq = (const float*)d_in[4];
    const float* Wk = (const float*)d_in[5];
    const float* bk = (const float*)d_in[6];
    const float* Wv = (const float*)d_in[7];
    const float* bv = (const float*)d_in[8];
    const float* Wo = (const float*)d_in[9];
    const float* bo = (const float*)d_in[10];
    float* out = (float*)d_out;

    __half *aq, *akv, *aat, *wq, *wk, *wv, *wo, *qh, *kh, *vh;
    cudaGetSymbolAddress((void**)&aq, g_aq);
    cudaGetSymbolAddress((void**)&akv, g_akv);
    cudaGetSymbolAddress((void**)&aat, g_aat);
    cudaGetSymbolAddress((void**)&wq, g_wq);
    cudaGetSymbolAddress((void**)&wk, g_wk);
    cudaGetSymbolAddress((void**)&wv, g_wv);
    cudaGetSymbolAddress((void**)&wo, g_wo);
    cudaGetSymbolAddress((void**)&qh, g_qh);
    cudaGetSymbolAddress((void**)&kh, g_kh);
    cudaGetSymbolAddress((void**)&vh, g_vh);

    const int gsmem = GSTAGES * STAGE_BYTES;  // 96KB
    cudaFuncSetAttribute(gemm_f32, cudaFuncAttributeMaxDynamicSharedMemorySize, gsmem);
    cudaFuncSetAttribute(gemm_h, cudaFuncAttributeMaxDynamicSharedMemorySize, gsmem);
    const int fsmem = FQ_BYTES + F_STAGES * FST_BYTES + 1024;  // 65KB
    cudaFuncSetAttribute(flash_hmma, cudaFuncAttributeMaxDynamicSharedMemorySize, fsmem);

    // conversions (batched)
    conv_w_all<<<dim3(32, 32, 4), dim3(32, 8)>>>(Wq, wq, Wk, wk, Wv, wv, Wo, wo);
    conv_act_all<<<dim3(MM * DD / 8 / 256, 2), 256>>>(Q, aq, K_V, akv);

    // projections (plain fp16, fp32 accumulate)
    dim3 gg(DD / 128, MM / 128);
    gemm_h<<<gg, 256, gsmem>>>(aq,  wq, bq, qh);
    gemm_h<<<gg, 256, gsmem>>>(akv, wk, bk, kh);
    gemm_h<<<gg, 256, gsmem>>>(akv, wv, bv, vh);

    // flash attention -> aat fp16
    flash_hmma<<<dim3(SS / 128, BB * HH), 256, fsmem>>>(qh, kh, vh, aat);

    // output projection (fp32 out)
    gemm_f32<<<gg, 256, gsmem>>>(aat, wo, bo, out);
}